// round 1
// baseline (speedup 1.0000x reference)
#include <cuda_runtime.h>
#include <cstdint>

#define BB   4
#define SEQ  8192
#define DIM  256
#define NH   8
#define HD   32
#define MTOT (BB*SEQ)        // 32768
#define QCH  64              // q-stats partial chunks
#define CCH  32              // ctx partial chunks (256 rows each)

// ---------------- scratch (device globals; no runtime allocation) ----------
__device__ float g_qbuf[BB*SEQ*DIM];          // 33.5 MB
__device__ float g_kbuf[BB*SEQ*DIM];
__device__ float g_vbuf[BB*SEQ*DIM];
__device__ float g_cat [BB*SEQ*3*DIM];        // 100.7 MB concat buffer
__device__ float g_ctx [BB*NH*HD*HD];
__device__ float g_ctxp[BB*NH*CCH*HD*HD];     // 4 MB partials
__device__ float g_qm  [BB*DIM];
__device__ float g_qs  [BB*DIM];
__device__ float g_qmp [BB*QCH*DIM];
__device__ float g_qsp [BB*QCH*DIM];

// ---------------- GEMM: C[M,256] = (A (+A2)) [M,K] @ W[K,256] + bias -------
// 128x128 block tile, BK=8, 256 threads, 8x8 per-thread microtile.
template<bool ADD2>
__global__ void __launch_bounds__(256, 2)
gemm_bias_kernel(const float* __restrict__ A, const float* __restrict__ A2,
                 const float* __restrict__ W, const float* __restrict__ bias,
                 float* __restrict__ C, int K)
{
    const int BM = 128, BN = 128, BK = 8;
    __shared__ float As[BK][BM];
    __shared__ float Bs[BK][BN];

    int tid  = threadIdx.x;
    int row0 = blockIdx.y * BM;
    int col0 = blockIdx.x * BN;

    int arow = tid >> 1;            // 0..127
    int acol = (tid & 1) * 4;       // 0 or 4
    int brow = tid >> 5;            // 0..7
    int bcol = (tid & 31) * 4;      // 0..124

    const float* Ap  = A + (size_t)(row0 + arow) * K + acol;
    const float* A2p = ADD2 ? (A2 + (size_t)(row0 + arow) * K + acol) : A;
    const float* Wp  = W + (size_t)brow * 256 + col0 + bcol;

    int tm = (tid >> 4) * 8;
    int tn = (tid & 15) * 8;

    float acc[8][8];
#pragma unroll
    for (int i = 0; i < 8; i++)
#pragma unroll
        for (int j = 0; j < 8; j++) acc[i][j] = 0.f;

    for (int k0 = 0; k0 < K; k0 += BK) {
        float4 av = *reinterpret_cast<const float4*>(Ap + k0);
        if (ADD2) {
            float4 a2 = *reinterpret_cast<const float4*>(A2p + k0);
            av.x += a2.x; av.y += a2.y; av.z += a2.z; av.w += a2.w;
        }
        float4 bv = *reinterpret_cast<const float4*>(Wp + (size_t)k0 * 256);

        As[acol + 0][arow] = av.x;
        As[acol + 1][arow] = av.y;
        As[acol + 2][arow] = av.z;
        As[acol + 3][arow] = av.w;
        *reinterpret_cast<float4*>(&Bs[brow][bcol]) = bv;
        __syncthreads();

#pragma unroll
        for (int kk = 0; kk < BK; kk++) {
            float ar[8], br[8];
#pragma unroll
            for (int i = 0; i < 8; i++) ar[i] = As[kk][tm + i];
#pragma unroll
            for (int j = 0; j < 8; j++) br[j] = Bs[kk][tn + j];
#pragma unroll
            for (int i = 0; i < 8; i++)
#pragma unroll
                for (int j = 0; j < 8; j++)
                    acc[i][j] += ar[i] * br[j];
        }
        __syncthreads();
    }

    float bb[8];
#pragma unroll
    for (int j = 0; j < 8; j++) bb[j] = bias[col0 + tn + j];
#pragma unroll
    for (int i = 0; i < 8; i++) {
        float* Cp = C + (size_t)(row0 + tm + i) * 256 + col0 + tn;
        float4 v0 = make_float4(acc[i][0] + bb[0], acc[i][1] + bb[1],
                                acc[i][2] + bb[2], acc[i][3] + bb[3]);
        float4 v1 = make_float4(acc[i][4] + bb[4], acc[i][5] + bb[5],
                                acc[i][6] + bb[6], acc[i][7] + bb[7]);
        reinterpret_cast<float4*>(Cp)[0] = v0;
        reinterpret_cast<float4*>(Cp)[1] = v1;
    }
}

// ---------------- q softmax stats over sequence axis (per b, channel) ------
__global__ void qstats_part_kernel()
{
    int b = blockIdx.x, ch = blockIdx.y, c = threadIdx.x;   // 256 threads
    const int ROWS = SEQ / QCH;                              // 128
    const float* p = g_qbuf + ((size_t)b * SEQ + (size_t)ch * ROWS) * DIM + c;
    float m = -1e30f, s = 0.f;
    for (int r = 0; r < ROWS; r++) {
        float x  = p[(size_t)r * DIM];
        float nm = fmaxf(m, x);
        s = s * __expf(m - nm) + __expf(x - nm);
        m = nm;
    }
    g_qmp[(b * QCH + ch) * DIM + c] = m;
    g_qsp[(b * QCH + ch) * DIM + c] = s;
}

__global__ void qstats_reduce_kernel()
{
    int b = blockIdx.x, c = threadIdx.x;
    float m = -1e30f;
    for (int ch = 0; ch < QCH; ch++)
        m = fmaxf(m, g_qmp[(b * QCH + ch) * DIM + c]);
    float s = 0.f;
    for (int ch = 0; ch < QCH; ch++)
        s += g_qsp[(b * QCH + ch) * DIM + c] * __expf(g_qmp[(b * QCH + ch) * DIM + c] - m);
    g_qm[b * DIM + c] = m;
    g_qs[b * DIM + c] = s;
}

// ---------------- ctx = softmax_c(k)^T v  (per b,h; chunked partials) ------
__global__ void __launch_bounds__(1024)
ctx_part_kernel()
{
    int blk   = blockIdx.x;                  // b*256 + h*32 + chunk
    int chunk = blk & (CCH - 1);
    int h     = (blk >> 5) & (NH - 1);
    int b     = blk >> 8;
    int tid   = threadIdx.x;
    int r = tid >> 5, col = tid & 31;        // load coords
    int c = r, d = col;                      // accumulate coords

    __shared__ float ks[32][33];
    __shared__ float vs[32][33];

    float acc = 0.f;
    const size_t base = ((size_t)b * SEQ + (size_t)chunk * (SEQ / CCH)) * DIM + h * HD;

    for (int t = 0; t < (SEQ / CCH) / 32; t++) {           // 8 tiles of 32 rows
        float kv = g_kbuf[base + (size_t)(t * 32 + r) * DIM + col];
        float vv = g_vbuf[base + (size_t)(t * 32 + r) * DIM + col];
        // k softmax over the 32 head channels (warp r == one row)
        float mx = kv;
#pragma unroll
        for (int o = 16; o; o >>= 1) mx = fmaxf(mx, __shfl_xor_sync(0xffffffffu, mx, o));
        float e = __expf(kv - mx);
        float sm = e;
#pragma unroll
        for (int o = 16; o; o >>= 1) sm += __shfl_xor_sync(0xffffffffu, sm, o);
        __syncthreads();                     // previous tile fully consumed
        ks[r][col] = e / sm;
        vs[r][col] = vv;
        __syncthreads();
#pragma unroll
        for (int rr = 0; rr < 32; rr++)
            acc += ks[rr][c] * vs[rr][d];
    }
    g_ctxp[(size_t)blk * (HD * HD) + tid] = acc;
}

__global__ void __launch_bounds__(1024)
ctx_reduce_kernel()
{
    int bh = blockIdx.x, tid = threadIdx.x;
    float s = 0.f;
    for (int ch = 0; ch < CCH; ch++)
        s += g_ctxp[((size_t)bh * CCH + ch) * (HD * HD) + tid];
    g_ctx[bh * (HD * HD) + tid] = s;
}

// ---------------- attend: cat[b,n,off+h*32+d] = sum_c ctx[c,d]*softq[c] ----
__global__ void __launch_bounds__(256)
att_kernel(int colOff)
{
    const int RB = 32;
    int blk = blockIdx.x;
    int b   = blk / (SEQ / RB);
    int n0  = (blk % (SEQ / RB)) * RB;
    int tid = threadIdx.x;
    int h = tid >> 5, d = tid & 31;

    __shared__ float ctx_s[NH * HD * HD];    // 32 KB
    for (int i = tid; i < NH * HD * HD; i += 256)
        ctx_s[i] = g_ctx[b * NH * HD * HD + i];

    float qm     = g_qm[b * DIM + tid];
    float inv_qs = 1.f / g_qs[b * DIM + tid];
    __syncthreads();

    const float* qrow = g_qbuf + ((size_t)b * SEQ + n0) * DIM;
    float*       orow = g_cat  + ((size_t)b * SEQ + n0) * (3 * DIM) + colOff;

    for (int n = 0; n < RB; n++) {
        float qv = qrow[(size_t)n * DIM + tid];
        float sq = __expf(qv - qm) * inv_qs;
        float acc = 0.f;
#pragma unroll
        for (int c = 0; c < 32; c++) {
            float sc = __shfl_sync(0xffffffffu, sq, c);
            acc += ctx_s[h * (HD * HD) + c * HD + d] * sc;
        }
        orow[(size_t)n * (3 * DIM) + h * HD + d] = acc;
    }
}

// ---------------- launcher -------------------------------------------------
extern "C" void kernel_launch(void* const* d_in, const int* in_sizes, int n_in,
                              void* d_out, int out_size)
{
    const float* f[4]   = {(const float*)d_in[0], (const float*)d_in[1],
                           (const float*)d_in[2], (const float*)d_in[3]};
    const float* fpe[4] = {(const float*)d_in[4], (const float*)d_in[5],
                           (const float*)d_in[6], (const float*)d_in[7]};
    const float* Wq  = (const float*)d_in[8];
    const float* bq  = (const float*)d_in[9];
    const float* Wk  = (const float*)d_in[10];
    const float* bk  = (const float*)d_in[11];
    const float* Wv  = (const float*)d_in[12];
    const float* bv  = (const float*)d_in[13];
    const float* Wrp = (const float*)d_in[14];
    const float* brp = (const float*)d_in[15];
    float* out = (float*)d_out;

    float *qbuf, *kbuf, *vbuf, *cat;
    cudaGetSymbolAddress((void**)&qbuf, g_qbuf);
    cudaGetSymbolAddress((void**)&kbuf, g_kbuf);
    cudaGetSymbolAddress((void**)&vbuf, g_vbuf);
    cudaGetSymbolAddress((void**)&cat,  g_cat);

    dim3 gg(2, MTOT / 128);   // (256-col / 128, 32768 / 128)

    for (int i = 0; i < 3; i++) {
        gemm_bias_kernel<true ><<<gg, 256>>>(f[0],     fpe[0],     Wq + i*DIM*DIM, bq + i*DIM, qbuf, DIM);
        gemm_bias_kernel<true ><<<gg, 256>>>(f[i + 1], fpe[i + 1], Wk + i*DIM*DIM, bk + i*DIM, kbuf, DIM);
        gemm_bias_kernel<false><<<gg, 256>>>(f[i + 1], nullptr,    Wv + i*DIM*DIM, bv + i*DIM, vbuf, DIM);

        qstats_part_kernel  <<<dim3(BB, QCH), 256>>>();
        qstats_reduce_kernel<<<BB, 256>>>();

        ctx_part_kernel  <<<BB * NH * CCH, 1024>>>();
        ctx_reduce_kernel<<<BB * NH, 1024>>>();

        att_kernel<<<BB * (SEQ / 32), 256>>>(i * DIM);
    }

    gemm_bias_kernel<false><<<gg, 256>>>(cat, nullptr, Wrp, brp, out, 3 * DIM);
}

// round 3
// speedup vs baseline: 1.5333x; 1.5333x over previous
#include <cuda_runtime.h>
#include <cuda_bf16.h>
#include <cstdint>

#define BB   4
#define SEQ  8192
#define DIM  256
#define NH   8
#define HD   32
#define MTOT (BB*SEQ)        // 32768
#define QCH  64
#define CCH  32

// ===================== scratch (device globals) =====================
// activations: 7 slots (q_in, k2,k3,k4, v2,v3,v4), each [MTOT][512] = [hi(256)|lo(256)]
__device__ __nv_bfloat16 g_a[7ull * MTOT * 512];
// concat buffer: [MTOT][1536] = [hi(768)|lo(768)]
__device__ __nv_bfloat16 g_c[(size_t)MTOT * 1536];
// weights transposed [N=256][2K]: 9 QKV (2K=512) + final (2K=1536)
__device__ __nv_bfloat16 g_w[9 * 131072 + 393216];
__device__ float g_qbuf[(size_t)MTOT * DIM];
__device__ float g_kbuf[(size_t)MTOT * DIM];
__device__ float g_vbuf[(size_t)MTOT * DIM];
__device__ float g_ctx [BB * NH * HD * HD];
__device__ float g_ctxp[BB * NH * CCH * HD * HD];
__device__ float g_qm  [BB * DIM];
__device__ float g_qs  [BB * DIM];
__device__ float g_qmp [BB * QCH * DIM];
__device__ float g_qsp [BB * QCH * DIM];

// ===================== helpers =====================
__device__ __forceinline__ uint32_t smem_u32(const void* p){
    uint32_t a;
    asm("{ .reg .u64 t; cvta.to.shared.u64 t, %1; cvt.u32.u64 %0, t; }" : "=r"(a) : "l"(p));
    return a;
}
__device__ __forceinline__ void cp16(uint32_t dst, const void* src){
    asm volatile("cp.async.cg.shared.global [%0], [%1], 16;" :: "r"(dst), "l"(src) : "memory");
}
__device__ __forceinline__ void cp_commit(){ asm volatile("cp.async.commit_group;" ::: "memory"); }
__device__ __forceinline__ void cp_wait1(){ asm volatile("cp.async.wait_group 1;" ::: "memory"); }
__device__ __forceinline__ void cp_wait0(){ asm volatile("cp.async.wait_group 0;" ::: "memory"); }

__device__ __forceinline__ void ldsm4(uint32_t& r0, uint32_t& r1, uint32_t& r2, uint32_t& r3, uint32_t addr){
    asm volatile("ldmatrix.sync.aligned.m8n8.x4.shared.b16 {%0,%1,%2,%3}, [%4];"
        : "=r"(r0), "=r"(r1), "=r"(r2), "=r"(r3) : "r"(addr));
}
__device__ __forceinline__ void mma16816(float* d, const uint32_t* a, const uint32_t* b){
    asm volatile("mma.sync.aligned.m16n8k16.row.col.f32.bf16.bf16.f32 "
        "{%0,%1,%2,%3}, {%4,%5,%6,%7}, {%8,%9}, {%0,%1,%2,%3};"
        : "+f"(d[0]), "+f"(d[1]), "+f"(d[2]), "+f"(d[3])
        : "r"(a[0]), "r"(a[1]), "r"(a[2]), "r"(a[3]), "r"(b[0]), "r"(b[1]));
}

// ===================== GEMM (warp-MMA, bf16x3 via K-remap) =====================
// C[M,256] = A' @ B'^T + bias, where K' = 3*KH*32, walked as [AhiBhi][AloBhi][AhiBlo].
// A stored [row][2*KH*32] = [hi|lo]; B stored [n][2*KH*32] = [hi|lo].
#define LDP 40            // padded smem row length (bf16 elems) -> 80 bytes
#define STG_BYTES 20480   // (128*LDP*2) * 2 tiles

__global__ void __launch_bounds__(256, 2)
gemm_mma(const __nv_bfloat16* __restrict__ A, int lda,
         const __nv_bfloat16* __restrict__ B, int ldb,
         const float* __restrict__ bias, float* __restrict__ C, int KH)
{
    __shared__ __align__(16) char smem[2 * STG_BYTES];
    const int tid  = threadIdx.x;
    const int lane = tid & 31, wid = tid >> 5;
    const int wm = wid >> 2, wn = wid & 3;            // warp grid 2x4
    const int row0 = blockIdx.y * 128;
    const int col0 = blockIdx.x * 128;
    const int nkc = 3 * KH;

    float acc[4][4][4];
#pragma unroll
    for (int i = 0; i < 4; i++)
#pragma unroll
        for (int j = 0; j < 4; j++)
#pragma unroll
            for (int v = 0; v < 4; v++) acc[i][j][v] = 0.f;

    const uint32_t smem_base = smem_u32(smem);
    // loader coords: 2 chunks per thread per tile
    const int ch0 = tid * 2;

    auto prefetch = [&](int kc) {
        int s = kc & 1;
        int a_k = (kc < 2 * KH) ? kc : kc - 2 * KH;   // hi, lo, hi
        int b_k = (kc < KH)     ? kc : kc - KH;       // hi, hi, lo
        uint32_t As = smem_base + s * STG_BYTES;
        uint32_t Bs = As + 10240;
#pragma unroll
        for (int t = 0; t < 2; t++) {
            int ch = ch0 + t;
            int r = ch >> 2, c = ch & 3;
            cp16(As + r * 80 + c * 16,
                 A + (size_t)(row0 + r) * lda + a_k * 32 + c * 8);
            cp16(Bs + r * 80 + c * 16,
                 B + (size_t)(col0 + r) * ldb + b_k * 32 + c * 8);
        }
        cp_commit();
    };

    prefetch(0);

    const int arow = lane & 15, acolh = (lane >> 4) * 8;
    const int bn   = (lane & 7) + (lane >> 4) * 8;
    const int bkh  = ((lane >> 3) & 1) * 8;

    for (int kc = 0; kc < nkc; kc++) {
        if (kc + 1 < nkc) { prefetch(kc + 1); cp_wait1(); }
        else              { cp_wait0(); }
        __syncthreads();

        int s = kc & 1;
        uint32_t As = smem_base + s * STG_BYTES;
        uint32_t Bs = As + 10240;

#pragma unroll
        for (int kk = 0; kk < 32; kk += 16) {
            uint32_t af[4][4];
#pragma unroll
            for (int i = 0; i < 4; i++) {
                uint32_t addr = As + (wm * 64 + i * 16 + arow) * 80 + (kk + acolh) * 2;
                ldsm4(af[i][0], af[i][1], af[i][2], af[i][3], addr);
            }
            uint32_t bf[4][2];
#pragma unroll
            for (int jp = 0; jp < 2; jp++) {
                uint32_t addr = Bs + (wn * 32 + jp * 16 + bn) * 80 + (kk + bkh) * 2;
                ldsm4(bf[2*jp][0], bf[2*jp][1], bf[2*jp+1][0], bf[2*jp+1][1], addr);
            }
#pragma unroll
            for (int i = 0; i < 4; i++)
#pragma unroll
                for (int j = 0; j < 4; j++)
                    mma16816(acc[i][j], af[i], bf[j]);
        }
        __syncthreads();
    }

    // epilogue
    const int g = lane >> 2, tg = lane & 3;
    float2 bb[4];
#pragma unroll
    for (int j = 0; j < 4; j++) {
        int c = col0 + wn * 32 + j * 8 + 2 * tg;
        bb[j] = make_float2(bias[c], bias[c + 1]);
    }
#pragma unroll
    for (int i = 0; i < 4; i++) {
        int r = row0 + wm * 64 + i * 16 + g;
#pragma unroll
        for (int j = 0; j < 4; j++) {
            int c = col0 + wn * 32 + j * 8 + 2 * tg;
            *reinterpret_cast<float2*>(C + (size_t)r * 256 + c) =
                make_float2(acc[i][j][0] + bb[j].x, acc[i][j][1] + bb[j].y);
            *reinterpret_cast<float2*>(C + (size_t)(r + 8) * 256 + c) =
                make_float2(acc[i][j][2] + bb[j].x, acc[i][j][3] + bb[j].y);
        }
    }
}

// ===================== prep: fp32 (+add) -> bf16 [hi|lo] rows =====================
template<bool ADD>
__global__ void __launch_bounds__(256)
prep_act(const float* __restrict__ a, const float* __restrict__ b,
         __nv_bfloat16* __restrict__ o, int n4)
{
    int i = blockIdx.x * 256 + threadIdx.x;
    if (i >= n4) return;
    float4 x = reinterpret_cast<const float4*>(a)[i];
    if (ADD) {
        float4 y = reinterpret_cast<const float4*>(b)[i];
        x.x += y.x; x.y += y.y; x.z += y.z; x.w += y.w;
    }
    __nv_bfloat16 h0 = __float2bfloat16(x.x), h1 = __float2bfloat16(x.y);
    __nv_bfloat16 h2 = __float2bfloat16(x.z), h3 = __float2bfloat16(x.w);
    __nv_bfloat16 l0 = __float2bfloat16(x.x - __bfloat162float(h0));
    __nv_bfloat16 l1 = __float2bfloat16(x.y - __bfloat162float(h1));
    __nv_bfloat16 l2 = __float2bfloat16(x.z - __bfloat162float(h2));
    __nv_bfloat16 l3 = __float2bfloat16(x.w - __bfloat162float(h3));
    union { __nv_bfloat162 b2[2]; uint2 u; } H, L;
    H.b2[0] = __nv_bfloat162(h0, h1); H.b2[1] = __nv_bfloat162(h2, h3);
    L.b2[0] = __nv_bfloat162(l0, l1); L.b2[1] = __nv_bfloat162(l2, l3);
    int row = i >> 6, cu = i & 63;          // 64 uint2 per 256-col row
    reinterpret_cast<uint2*>(o)[row * 128 + cu]      = H.u;
    reinterpret_cast<uint2*>(o)[row * 128 + 64 + cu] = L.u;
}

// W[K,N] fp32 -> Wt[n][2K] = [hi(K)|lo(K)]
__global__ void __launch_bounds__(256)
prep_w(const float* __restrict__ W, __nv_bfloat16* __restrict__ o, int K, int N)
{
    int t = blockIdx.x * 256 + threadIdx.x;
    if (t >= K * N) return;
    int n = t / K, k = t - n * K;
    float x = W[(size_t)k * N + n];
    __nv_bfloat16 h = __float2bfloat16(x);
    o[(size_t)n * (2 * K) + k]     = h;
    o[(size_t)n * (2 * K) + K + k] = __float2bfloat16(x - __bfloat162float(h));
}

// ===================== q softmax stats over sequence axis =====================
__global__ void qstats_part_kernel()
{
    int b = blockIdx.x, ch = blockIdx.y, c = threadIdx.x;
    const int ROWS = SEQ / QCH;
    const float* p = g_qbuf + ((size_t)b * SEQ + (size_t)ch * ROWS) * DIM + c;
    float m0=-1e30f,m1=-1e30f,m2=-1e30f,m3=-1e30f, s0=0.f,s1=0.f,s2=0.f,s3=0.f;
    for (int r = 0; r < ROWS; r += 4) {
        float x0 = p[(size_t)(r+0)*DIM], x1 = p[(size_t)(r+1)*DIM];
        float x2 = p[(size_t)(r+2)*DIM], x3 = p[(size_t)(r+3)*DIM];
        float nm;
        nm = fmaxf(m0,x0); s0 = s0*__expf(m0-nm)+__expf(x0-nm); m0 = nm;
        nm = fmaxf(m1,x1); s1 = s1*__expf(m1-nm)+__expf(x1-nm); m1 = nm;
        nm = fmaxf(m2,x2); s2 = s2*__expf(m2-nm)+__expf(x2-nm); m2 = nm;
        nm = fmaxf(m3,x3); s3 = s3*__expf(m3-nm)+__expf(x3-nm); m3 = nm;
    }
    float m = fmaxf(fmaxf(m0,m1), fmaxf(m2,m3));
    float s = s0*__expf(m0-m) + s1*__expf(m1-m) + s2*__expf(m2-m) + s3*__expf(m3-m);
    g_qmp[(b*QCH+ch)*DIM+c] = m;
    g_qsp[(b*QCH+ch)*DIM+c] = s;
}

__global__ void qstats_reduce_kernel()
{
    int b = blockIdx.x, c = threadIdx.x;
    float m = -1e30f;
    for (int ch = 0; ch < QCH; ch++) m = fmaxf(m, g_qmp[(b*QCH+ch)*DIM+c]);
    float s = 0.f;
    for (int ch = 0; ch < QCH; ch++)
        s += g_qsp[(b*QCH+ch)*DIM+c] * __expf(g_qmp[(b*QCH+ch)*DIM+c] - m);
    g_qm[b*DIM+c] = m;
    g_qs[b*DIM+c] = s;
}

// ===================== ctx = softmax_c(k)^T v =====================
__global__ void __launch_bounds__(1024)
ctx_part_kernel()
{
    int blk = blockIdx.x;
    int chunk = blk & (CCH-1), hh = (blk>>5) & (NH-1), b = blk >> 8;
    int tid = threadIdx.x;
    int r = tid >> 5, col = tid & 31;
    int c = r, d = col;
    __shared__ float ks[32][33];
    __shared__ float vs[32][33];
    float acc = 0.f;
    const size_t base = ((size_t)b*SEQ + (size_t)chunk*(SEQ/CCH))*DIM + hh*HD;
    for (int t = 0; t < (SEQ/CCH)/32; t++) {
        float kv = g_kbuf[base + (size_t)(t*32+r)*DIM + col];
        float vv = g_vbuf[base + (size_t)(t*32+r)*DIM + col];
        float mx = kv;
        #pragma unroll
        for (int o = 16; o; o >>= 1) mx = fmaxf(mx, __shfl_xor_sync(0xffffffffu, mx, o));
        float e = __expf(kv - mx);
        float sm = e;
        #pragma unroll
        for (int o = 16; o; o >>= 1) sm += __shfl_xor_sync(0xffffffffu, sm, o);
        __syncthreads();
        ks[r][col] = e / sm;
        vs[r][col] = vv;
        __syncthreads();
        #pragma unroll
        for (int rr = 0; rr < 32; rr++) acc += ks[rr][c] * vs[rr][d];
    }
    g_ctxp[(size_t)blk*(HD*HD) + tid] = acc;
}

__global__ void __launch_bounds__(1024)
ctx_reduce_kernel()
{
    int bh = blockIdx.x, tid = threadIdx.x;
    float s = 0.f;
    for (int ch = 0; ch < CCH; ch++)
        s += g_ctxp[((size_t)bh*CCH+ch)*(HD*HD) + tid];
    g_ctx[bh*(HD*HD)+tid] = s;
}

// ===================== attend -> cat [hi|lo] rows (stride 1536) =====================
__global__ void __launch_bounds__(256)
att_kernel(int colOff)
{
    const int RB = 32;
    int blk = blockIdx.x;
    int b = blk / (SEQ/RB);
    int n0 = (blk % (SEQ/RB)) * RB;
    int tid = threadIdx.x;
    int hh = tid >> 5, d = tid & 31;

    __shared__ float ctx_s[NH*HD*HD];
    for (int i = tid; i < NH*HD*HD; i += 256)
        ctx_s[i] = g_ctx[b*NH*HD*HD + i];

    float qm = g_qm[b*DIM+tid];
    float inv_qs = 1.f / g_qs[b*DIM+tid];
    __syncthreads();

    const float* qrow = g_qbuf + ((size_t)b*SEQ + n0) * DIM;
    __nv_bfloat16* orow = g_c + ((size_t)b*SEQ + n0) * 1536 + colOff;

    for (int n = 0; n < RB; n++) {
        float qv = qrow[(size_t)n*DIM + tid];
        float sq = __expf(qv - qm) * inv_qs;
        float acc = 0.f;
        #pragma unroll
        for (int c = 0; c < 32; c++) {
            float sc = __shfl_sync(0xffffffffu, sq, c);
            acc += ctx_s[hh*(HD*HD) + c*HD + d] * sc;
        }
        size_t o = (size_t)n*1536 + hh*HD + d;
        __nv_bfloat16 hv = __float2bfloat16(acc);
        orow[o]       = hv;
        orow[o + 768] = __float2bfloat16(acc - __bfloat162float(hv));
    }
}

// ===================== launcher =====================
extern "C" void kernel_launch(void* const* d_in, const int* in_sizes, int n_in,
                              void* d_out, int out_size)
{
    const float* f[4]   = {(const float*)d_in[0], (const float*)d_in[1],
                           (const float*)d_in[2], (const float*)d_in[3]};
    const float* fpe[4] = {(const float*)d_in[4], (const float*)d_in[5],
                           (const float*)d_in[6], (const float*)d_in[7]};
    const float* Wq  = (const float*)d_in[8];
    const float* bq  = (const float*)d_in[9];
    const float* Wk  = (const float*)d_in[10];
    const float* bk  = (const float*)d_in[11];
    const float* Wv  = (const float*)d_in[12];
    const float* bv  = (const float*)d_in[13];
    const float* Wrp = (const float*)d_in[14];
    const float* brp = (const float*)d_in[15];
    float* out = (float*)d_out;

    float *qbuf, *kbuf, *vbuf;
    __nv_bfloat16 *abuf, *cbuf, *wbuf;
    cudaGetSymbolAddress((void**)&qbuf, g_qbuf);
    cudaGetSymbolAddress((void**)&kbuf, g_kbuf);
    cudaGetSymbolAddress((void**)&vbuf, g_vbuf);
    cudaGetSymbolAddress((void**)&abuf, g_a);
    cudaGetSymbolAddress((void**)&cbuf, g_c);
    cudaGetSymbolAddress((void**)&wbuf, g_w);

    const size_t AS = (size_t)MTOT * 512;     // elems per activation slot
    const int n4 = MTOT * DIM / 4;
    const int pb = n4 / 256;

    // activation prep: slot 0 = q_in, 1..3 = k-inputs, 4..6 = v-inputs
    prep_act<true ><<<pb, 256>>>(f[0], fpe[0], abuf, n4);
    for (int i = 1; i <= 3; i++) {
        prep_act<true ><<<pb, 256>>>(f[i], fpe[i], abuf + i * AS, n4);
        prep_act<false><<<pb, 256>>>(f[i], nullptr, abuf + (3 + i) * AS, n4);
    }
    // weights
    for (int i = 0; i < 3; i++) {
        prep_w<<<256, 256>>>(Wq + (size_t)i*DIM*DIM, wbuf + (3*i+0)*131072, 256, 256);
        prep_w<<<256, 256>>>(Wk + (size_t)i*DIM*DIM, wbuf + (3*i+1)*131072, 256, 256);
        prep_w<<<256, 256>>>(Wv + (size_t)i*DIM*DIM, wbuf + (3*i+2)*131072, 256, 256);
    }
    prep_w<<<768, 256>>>(Wrp, wbuf + 9*131072, 768, 256);

    dim3 gg(2, MTOT / 128);
    for (int i = 0; i < 3; i++) {
        gemm_mma<<<gg, 256>>>(abuf,            512, wbuf + (3*i+0)*131072, 512, bq + i*DIM, qbuf, 8);
        gemm_mma<<<gg, 256>>>(abuf + (1+i)*AS, 512, wbuf + (3*i+1)*131072, 512, bk + i*DIM, kbuf, 8);
        gemm_mma<<<gg, 256>>>(abuf + (4+i)*AS, 512, wbuf + (3*i+2)*131072, 512, bv + i*DIM, vbuf, 8);

        qstats_part_kernel  <<<dim3(BB, QCH), 256>>>();
        qstats_reduce_kernel<<<BB, 256>>>();

        ctx_part_kernel  <<<BB * NH * CCH, 1024>>>();
        ctx_reduce_kernel<<<BB * NH, 1024>>>();

        att_kernel<<<BB * (SEQ / 32), 256>>>(i * DIM);
    }

    gemm_mma<<<gg, 256>>>(cbuf, 1536, wbuf + 9*131072, 1536, brp, out, 24);
}

// round 4
// speedup vs baseline: 1.8975x; 1.2375x over previous
#include <cuda_runtime.h>
#include <cuda_bf16.h>
#include <cstdint>

#define BB   4
#define SEQ  8192
#define DIM  256
#define NH   8
#define HD   32
#define MTOT (BB*SEQ)        // 32768
#define QCH  128             // q-stats chunks (64 rows each)
#define CCH  32

// ===================== scratch (device globals) =====================
// activations: 7 slots (q_in, k2,k3,k4, v2,v3,v4), each [MTOT][512] = [hi(256)|lo(256)]
__device__ __nv_bfloat16 g_a[7ull * MTOT * 512];
// concat buffer: [MTOT][1536] = [hi(768)|lo(768)]
__device__ __nv_bfloat16 g_c[(size_t)MTOT * 1536];
// weights: q(768x512) | k 3x(256x512) | v 3x(256x512) | final(256x1536)
__device__ __nv_bfloat16 g_w[1572864];
__device__ float g_qall[(size_t)MTOT * 768];     // all 3 q projections
__device__ float g_kbuf[(size_t)MTOT * DIM];     // per-branch, reused
__device__ float g_vbuf[(size_t)MTOT * DIM];
__device__ float g_ctx [BB * 24 * HD * HD];      // [b][h24][c][d]
__device__ float g_ctxp[BB * NH * CCH * HD * HD];
__device__ float g_qm  [BB * 768];
__device__ float g_qs  [BB * 768];               // stores 1/sum
__device__ float g_qmp [BB * QCH * 768];
__device__ float g_qsp [BB * QCH * 768];

// ===================== helpers =====================
__device__ __forceinline__ uint32_t smem_u32(const void* p){
    uint32_t a;
    asm("{ .reg .u64 t; cvta.to.shared.u64 t, %1; cvt.u32.u64 %0, t; }" : "=r"(a) : "l"(p));
    return a;
}
__device__ __forceinline__ void cp16(uint32_t dst, const void* src){
    asm volatile("cp.async.cg.shared.global [%0], [%1], 16;" :: "r"(dst), "l"(src) : "memory");
}
__device__ __forceinline__ void cp_commit(){ asm volatile("cp.async.commit_group;" ::: "memory"); }
__device__ __forceinline__ void cp_wait1(){ asm volatile("cp.async.wait_group 1;" ::: "memory"); }
__device__ __forceinline__ void cp_wait0(){ asm volatile("cp.async.wait_group 0;" ::: "memory"); }

__device__ __forceinline__ void ldsm4(uint32_t& r0, uint32_t& r1, uint32_t& r2, uint32_t& r3, uint32_t addr){
    asm volatile("ldmatrix.sync.aligned.m8n8.x4.shared.b16 {%0,%1,%2,%3}, [%4];"
        : "=r"(r0), "=r"(r1), "=r"(r2), "=r"(r3) : "r"(addr));
}
__device__ __forceinline__ void mma16816(float* d, const uint32_t* a, const uint32_t* b){
    asm volatile("mma.sync.aligned.m16n8k16.row.col.f32.bf16.bf16.f32 "
        "{%0,%1,%2,%3}, {%4,%5,%6,%7}, {%8,%9}, {%0,%1,%2,%3};"
        : "+f"(d[0]), "+f"(d[1]), "+f"(d[2]), "+f"(d[3])
        : "r"(a[0]), "r"(a[1]), "r"(a[2]), "r"(a[3]), "r"(b[0]), "r"(b[1]));
}

// ===================== GEMM (warp-MMA, bf16x3 via K-remap) =====================
// C[M,N] = A' @ B'^T + bias, K' = 3*KH*32, walked as [AhiBhi][AloBhi][AhiBlo].
// blockIdx.z selects operand set (for batching k/v GEMMs).
#define STG_BYTES 20480   // (128+128) rows * 80B * ... per stage

__global__ void __launch_bounds__(256, 2)
gemm_mma(const __nv_bfloat16* __restrict__ A0, const __nv_bfloat16* __restrict__ A1, int lda,
         const __nv_bfloat16* __restrict__ B0, const __nv_bfloat16* __restrict__ B1, int ldb,
         const float* __restrict__ bias0, const float* __restrict__ bias1,
         float* __restrict__ C0, float* __restrict__ C1, int N, int KH)
{
    __shared__ __align__(16) char smem[2 * STG_BYTES];
    const __nv_bfloat16* A = blockIdx.z ? A1 : A0;
    const __nv_bfloat16* B = blockIdx.z ? B1 : B0;
    const float* bias      = blockIdx.z ? bias1 : bias0;
    float* C               = blockIdx.z ? C1 : C0;

    const int tid  = threadIdx.x;
    const int lane = tid & 31, wid = tid >> 5;
    const int wm = wid >> 2, wn = wid & 3;            // warp grid 2x4
    const int row0 = blockIdx.y * 128;
    const int col0 = blockIdx.x * 128;
    const int nkc = 3 * KH;

    float acc[4][4][4];
#pragma unroll
    for (int i = 0; i < 4; i++)
#pragma unroll
        for (int j = 0; j < 4; j++)
#pragma unroll
            for (int v = 0; v < 4; v++) acc[i][j][v] = 0.f;

    const uint32_t smem_base = smem_u32(smem);
    const int ch0 = tid * 2;

    auto prefetch = [&](int kc) {
        int s = kc & 1;
        int a_k = (kc < 2 * KH) ? kc : kc - 2 * KH;   // hi, lo, hi
        int b_k = (kc < KH)     ? kc : kc - KH;       // hi, hi, lo
        uint32_t As = smem_base + s * STG_BYTES;
        uint32_t Bs = As + 10240;
#pragma unroll
        for (int t = 0; t < 2; t++) {
            int ch = ch0 + t;
            int r = ch >> 2, c = ch & 3;
            cp16(As + r * 80 + c * 16,
                 A + (size_t)(row0 + r) * lda + a_k * 32 + c * 8);
            cp16(Bs + r * 80 + c * 16,
                 B + (size_t)(col0 + r) * ldb + b_k * 32 + c * 8);
        }
        cp_commit();
    };

    prefetch(0);

    const int arow = lane & 15, acolh = (lane >> 4) * 8;
    const int bn   = (lane & 7) + (lane >> 4) * 8;
    const int bkh  = ((lane >> 3) & 1) * 8;

    for (int kc = 0; kc < nkc; kc++) {
        if (kc + 1 < nkc) { prefetch(kc + 1); cp_wait1(); }
        else              { cp_wait0(); }
        __syncthreads();

        int s = kc & 1;
        uint32_t As = smem_base + s * STG_BYTES;
        uint32_t Bs = As + 10240;

#pragma unroll
        for (int kk = 0; kk < 32; kk += 16) {
            uint32_t af[4][4];
#pragma unroll
            for (int i = 0; i < 4; i++) {
                uint32_t addr = As + (wm * 64 + i * 16 + arow) * 80 + (kk + acolh) * 2;
                ldsm4(af[i][0], af[i][1], af[i][2], af[i][3], addr);
            }
            uint32_t bf[4][2];
#pragma unroll
            for (int jp = 0; jp < 2; jp++) {
                uint32_t addr = Bs + (wn * 32 + jp * 16 + bn) * 80 + (kk + bkh) * 2;
                ldsm4(bf[2*jp][0], bf[2*jp][1], bf[2*jp+1][0], bf[2*jp+1][1], addr);
            }
#pragma unroll
            for (int i = 0; i < 4; i++)
#pragma unroll
                for (int j = 0; j < 4; j++)
                    mma16816(acc[i][j], af[i], bf[j]);
        }
        __syncthreads();
    }

    const int g = lane >> 2, tg = lane & 3;
    float2 bb[4];
#pragma unroll
    for (int j = 0; j < 4; j++) {
        int c = col0 + wn * 32 + j * 8 + 2 * tg;
        bb[j] = make_float2(bias[c], bias[c + 1]);
    }
#pragma unroll
    for (int i = 0; i < 4; i++) {
        int r = row0 + wm * 64 + i * 16 + g;
#pragma unroll
        for (int j = 0; j < 4; j++) {
            int c = col0 + wn * 32 + j * 8 + 2 * tg;
            *reinterpret_cast<float2*>(C + (size_t)r * N + c) =
                make_float2(acc[i][j][0] + bb[j].x, acc[i][j][1] + bb[j].y);
            *reinterpret_cast<float2*>(C + (size_t)(r + 8) * N + c) =
                make_float2(acc[i][j][2] + bb[j].x, acc[i][j][3] + bb[j].y);
        }
    }
}

// ===================== prep kernels =====================
__device__ __forceinline__ void split4(float4 x, uint2& H, uint2& L)
{
    __nv_bfloat16 h0 = __float2bfloat16(x.x), h1 = __float2bfloat16(x.y);
    __nv_bfloat16 h2 = __float2bfloat16(x.z), h3 = __float2bfloat16(x.w);
    __nv_bfloat16 l0 = __float2bfloat16(x.x - __bfloat162float(h0));
    __nv_bfloat16 l1 = __float2bfloat16(x.y - __bfloat162float(h1));
    __nv_bfloat16 l2 = __float2bfloat16(x.z - __bfloat162float(h2));
    __nv_bfloat16 l3 = __float2bfloat16(x.w - __bfloat162float(h3));
    union { __nv_bfloat162 b2[2]; uint2 u; } HH, LL;
    HH.b2[0] = __nv_bfloat162(h0, h1); HH.b2[1] = __nv_bfloat162(h2, h3);
    LL.b2[0] = __nv_bfloat162(l0, l1); LL.b2[1] = __nv_bfloat162(l2, l3);
    H = HH.u; L = LL.u;
}

// q_in = a + b, rows [hi(256)|lo(256)]
__global__ void __launch_bounds__(256)
prep_q(const float* __restrict__ a, const float* __restrict__ b,
       __nv_bfloat16* __restrict__ o, int n4)
{
    int i = blockIdx.x * 256 + threadIdx.x;
    if (i >= n4) return;
    float4 x = reinterpret_cast<const float4*>(a)[i];
    float4 y = reinterpret_cast<const float4*>(b)[i];
    x.x += y.x; x.y += y.y; x.z += y.z; x.w += y.w;
    uint2 H, L; split4(x, H, L);
    int row = i >> 6, cu = i & 63;
    reinterpret_cast<uint2*>(o)[row * 128 + cu]      = H;
    reinterpret_cast<uint2*>(o)[row * 128 + 64 + cu] = L;
}

// k slot = f+pe, v slot = f; one read of f
__global__ void __launch_bounds__(256)
prep_kv(const float* __restrict__ f, const float* __restrict__ pe,
        __nv_bfloat16* __restrict__ ok, __nv_bfloat16* __restrict__ ov, int n4)
{
    int i = blockIdx.x * 256 + threadIdx.x;
    if (i >= n4) return;
    float4 x = reinterpret_cast<const float4*>(f)[i];
    float4 y = reinterpret_cast<const float4*>(pe)[i];
    float4 k = make_float4(x.x + y.x, x.y + y.y, x.z + y.z, x.w + y.w);
    uint2 H, L;
    int row = i >> 6, cu = i & 63;
    split4(k, H, L);
    reinterpret_cast<uint2*>(ok)[row * 128 + cu]      = H;
    reinterpret_cast<uint2*>(ok)[row * 128 + 64 + cu] = L;
    split4(x, H, L);
    reinterpret_cast<uint2*>(ov)[row * 128 + cu]      = H;
    reinterpret_cast<uint2*>(ov)[row * 128 + 64 + cu] = L;
}

// W[K,N] fp32 -> Wt[n][2K] = [hi(K)|lo(K)]
__global__ void __launch_bounds__(256)
prep_w(const float* __restrict__ W, __nv_bfloat16* __restrict__ o, int K, int N)
{
    int t = blockIdx.x * 256 + threadIdx.x;
    if (t >= K * N) return;
    int n = t / K, k = t - n * K;
    float x = W[(size_t)k * N + n];
    __nv_bfloat16 h = __float2bfloat16(x);
    o[(size_t)n * (2 * K) + k]     = h;
    o[(size_t)n * (2 * K) + K + k] = __float2bfloat16(x - __bfloat162float(h));
}

// ===================== q softmax stats over sequence axis (768 ch) ==========
__global__ void qstats_part_kernel()
{
    int b = blockIdx.x, ch = blockIdx.y, c = blockIdx.z * 256 + threadIdx.x;
    const int ROWS = SEQ / QCH;                       // 64
    const float* p = g_qall + ((size_t)b * SEQ + (size_t)ch * ROWS) * 768 + c;
    float m0=-1e30f,m1=-1e30f,m2=-1e30f,m3=-1e30f, s0=0.f,s1=0.f,s2=0.f,s3=0.f;
    for (int r = 0; r < ROWS; r += 4) {
        float x0 = p[(size_t)(r+0)*768], x1 = p[(size_t)(r+1)*768];
        float x2 = p[(size_t)(r+2)*768], x3 = p[(size_t)(r+3)*768];
        float nm;
        nm = fmaxf(m0,x0); s0 = s0*__expf(m0-nm)+__expf(x0-nm); m0 = nm;
        nm = fmaxf(m1,x1); s1 = s1*__expf(m1-nm)+__expf(x1-nm); m1 = nm;
        nm = fmaxf(m2,x2); s2 = s2*__expf(m2-nm)+__expf(x2-nm); m2 = nm;
        nm = fmaxf(m3,x3); s3 = s3*__expf(m3-nm)+__expf(x3-nm); m3 = nm;
    }
    float m = fmaxf(fmaxf(m0,m1), fmaxf(m2,m3));
    float s = s0*__expf(m0-m) + s1*__expf(m1-m) + s2*__expf(m2-m) + s3*__expf(m3-m);
    g_qmp[((size_t)b*QCH+ch)*768 + c] = m;
    g_qsp[((size_t)b*QCH+ch)*768 + c] = s;
}

__global__ void qstats_reduce_kernel()
{
    int b = blockIdx.x, c = blockIdx.y * 256 + threadIdx.x;
    float m = -1e30f;
    for (int ch = 0; ch < QCH; ch++) m = fmaxf(m, g_qmp[((size_t)b*QCH+ch)*768 + c]);
    float s = 0.f;
    for (int ch = 0; ch < QCH; ch++)
        s += g_qsp[((size_t)b*QCH+ch)*768 + c] * __expf(g_qmp[((size_t)b*QCH+ch)*768 + c] - m);
    g_qm[b*768 + c] = m;
    g_qs[b*768 + c] = 1.f / s;
}

// ===================== ctx = softmax_c(k)^T v (per branch) =====================
__global__ void __launch_bounds__(1024)
ctx_part_kernel()
{
    int blk = blockIdx.x;
    int chunk = blk & (CCH-1), hh = (blk>>5) & (NH-1), b = blk >> 8;
    int tid = threadIdx.x;
    int r = tid >> 5, col = tid & 31;
    int c = r, d = col;
    __shared__ float ks[32][33];
    __shared__ float vs[32][33];
    float acc = 0.f;
    const size_t base = ((size_t)b*SEQ + (size_t)chunk*(SEQ/CCH))*DIM + hh*HD;
    for (int t = 0; t < (SEQ/CCH)/32; t++) {
        float kv = g_kbuf[base + (size_t)(t*32+r)*DIM + col];
        float vv = g_vbuf[base + (size_t)(t*32+r)*DIM + col];
        float mx = kv;
        #pragma unroll
        for (int o = 16; o; o >>= 1) mx = fmaxf(mx, __shfl_xor_sync(0xffffffffu, mx, o));
        float e = __expf(kv - mx);
        float sm = e;
        #pragma unroll
        for (int o = 16; o; o >>= 1) sm += __shfl_xor_sync(0xffffffffu, sm, o);
        __syncthreads();
        ks[r][col] = e / sm;
        vs[r][col] = vv;
        __syncthreads();
        #pragma unroll
        for (int rr = 0; rr < 32; rr++) acc += ks[rr][c] * vs[rr][d];
    }
    g_ctxp[(size_t)blk*(HD*HD) + tid] = acc;
}

// writes g_ctx[b][branch*8 + h][c][d]
__global__ void __launch_bounds__(1024)
ctx_reduce_kernel(int branch)
{
    int bh = blockIdx.x, tid = threadIdx.x;   // bh = b*8 + h
    int b = bh >> 3, h = bh & 7;
    float s = 0.f;
    for (int ch = 0; ch < CCH; ch++)
        s += g_ctxp[((size_t)bh*CCH+ch)*(HD*HD) + tid];
    g_ctx[((size_t)b*24 + branch*8 + h)*(HD*HD) + tid] = s;
}

// ===================== attend: all 3 branches, ctx in registers ==============
// block: 384 threads, 32 rows; thread -> channels (2*tid, 2*tid+1), head h24 = tid>>4
__global__ void __launch_bounds__(384, 1)
att_kernel()
{
    __shared__ float sq_s[8][768];
    __shared__ float qm_s[768];
    __shared__ float qi_s[768];

    int blk = blockIdx.x;
    int b   = blk / (SEQ/32);
    int n0  = (blk % (SEQ/32)) * 32;
    int tid = threadIdx.x;
    int ch0 = tid * 2;
    int h24 = ch0 >> 5;
    int d0  = ch0 & 31;

    // ctx registers: 32 c x 2 d
    float cr[32][2];
    const float* cp = g_ctx + ((size_t)b*24 + h24) * (HD*HD) + d0;
    #pragma unroll
    for (int c = 0; c < 32; c++) {
        float2 v = *reinterpret_cast<const float2*>(cp + c*32);
        cr[c][0] = v.x; cr[c][1] = v.y;
    }
    // stage stats
    {
        float2 m2 = *reinterpret_cast<const float2*>(g_qm + b*768 + ch0);
        float2 i2 = *reinterpret_cast<const float2*>(g_qs + b*768 + ch0);
        qm_s[ch0] = m2.x; qm_s[ch0+1] = m2.y;
        qi_s[ch0] = i2.x; qi_s[ch0+1] = i2.y;
    }
    __syncthreads();

    const float* qrow = g_qall + ((size_t)b*SEQ + n0) * 768;
    __nv_bfloat16* orow = g_c + ((size_t)b*SEQ + n0) * 1536;

    for (int chunk = 0; chunk < 4; chunk++) {
        // fill sq_s: 8 rows x 768 = 1536 float4 by 384 threads
        #pragma unroll
        for (int v = 0; v < 4; v++) {
            int idx = v * 384 + tid;
            int r = idx / 192, col = (idx - r * 192) * 4;
            float4 x = *reinterpret_cast<const float4*>(qrow + (size_t)(chunk*8 + r)*768 + col);
            float4 m = *reinterpret_cast<const float4*>(qm_s + col);
            float4 iv = *reinterpret_cast<const float4*>(qi_s + col);
            float4 sq = make_float4(__expf(x.x - m.x) * iv.x, __expf(x.y - m.y) * iv.y,
                                    __expf(x.z - m.z) * iv.z, __expf(x.w - m.w) * iv.w);
            *reinterpret_cast<float4*>(&sq_s[r][col]) = sq;
        }
        __syncthreads();

        #pragma unroll
        for (int n = 0; n < 8; n++) {
            float4 s4[8];
            const float4* sp = reinterpret_cast<const float4*>(&sq_s[n][h24 * 32]);
            #pragma unroll
            for (int u = 0; u < 8; u++) s4[u] = sp[u];
            const float* s = reinterpret_cast<const float*>(s4);
            float a0 = 0.f, a1 = 0.f;
            #pragma unroll
            for (int c = 0; c < 32; c++) { a0 += cr[c][0] * s[c]; a1 += cr[c][1] * s[c]; }

            size_t ro = (size_t)(chunk*8 + n) * 1536;
            __nv_bfloat16 h0 = __float2bfloat16(a0);
            __nv_bfloat16 h1 = __float2bfloat16(a1);
            __nv_bfloat16 l0 = __float2bfloat16(a0 - __bfloat162float(h0));
            __nv_bfloat16 l1 = __float2bfloat16(a1 - __bfloat162float(h1));
            *reinterpret_cast<__nv_bfloat162*>(orow + ro + ch0)       = __nv_bfloat162(h0, h1);
            *reinterpret_cast<__nv_bfloat162*>(orow + ro + 768 + ch0) = __nv_bfloat162(l0, l1);
        }
        __syncthreads();
    }
}

// ===================== launcher =====================
extern "C" void kernel_launch(void* const* d_in, const int* in_sizes, int n_in,
                              void* d_out, int out_size)
{
    const float* f[4]   = {(const float*)d_in[0], (const float*)d_in[1],
                           (const float*)d_in[2], (const float*)d_in[3]};
    const float* fpe[4] = {(const float*)d_in[4], (const float*)d_in[5],
                           (const float*)d_in[6], (const float*)d_in[7]};
    const float* Wq  = (const float*)d_in[8];
    const float* bq  = (const float*)d_in[9];
    const float* Wk  = (const float*)d_in[10];
    const float* bk  = (const float*)d_in[11];
    const float* Wv  = (const float*)d_in[12];
    const float* bv  = (const float*)d_in[13];
    const float* Wrp = (const float*)d_in[14];
    const float* brp = (const float*)d_in[15];
    float* out = (float*)d_out;

    float *qall, *kbuf, *vbuf;
    __nv_bfloat16 *abuf, *cbuf, *wbuf;
    cudaGetSymbolAddress((void**)&qall, g_qall);
    cudaGetSymbolAddress((void**)&kbuf, g_kbuf);
    cudaGetSymbolAddress((void**)&vbuf, g_vbuf);
    cudaGetSymbolAddress((void**)&abuf, g_a);
    cudaGetSymbolAddress((void**)&cbuf, g_c);
    cudaGetSymbolAddress((void**)&wbuf, g_w);

    const size_t AS = (size_t)MTOT * 512;
    const int n4 = MTOT * DIM / 4;
    const int pb = n4 / 256;

    // weight layout offsets (elements)
    __nv_bfloat16* wq = wbuf;                    // 768 x 512
    __nv_bfloat16* wk = wbuf + 393216;           // 3 x 256 x 512
    __nv_bfloat16* wv = wbuf + 786432;
    __nv_bfloat16* wf = wbuf + 1179648;          // 256 x 1536

    // activation prep
    prep_q<<<pb, 256>>>(f[0], fpe[0], abuf, n4);
    for (int i = 1; i <= 3; i++)
        prep_kv<<<pb, 256>>>(f[i], fpe[i], abuf + i * AS, abuf + (3 + i) * AS, n4);

    // weight prep
    for (int i = 0; i < 3; i++) {
        prep_w<<<256, 256>>>(Wq + (size_t)i*DIM*DIM, wq + (size_t)i*256*512, 256, 256);
        prep_w<<<256, 256>>>(Wk + (size_t)i*DIM*DIM, wk + (size_t)i*131072, 256, 256);
        prep_w<<<256, 256>>>(Wv + (size_t)i*DIM*DIM, wv + (size_t)i*131072, 256, 256);
    }
    prep_w<<<768, 256>>>(Wrp, wf, 768, 256);

    // qall = q_in @ [Wq0|Wq1|Wq2]  (N=768)
    gemm_mma<<<dim3(6, MTOT/128, 1), 256>>>(abuf, abuf, 512, wq, wq, 512,
                                            bq, bq, qall, qall, 768, 8);

    for (int i = 0; i < 3; i++) {
        // k_i and v_i in one batched launch (z=2)
        gemm_mma<<<dim3(2, MTOT/128, 2), 256>>>(
            abuf + (1+i)*AS, abuf + (4+i)*AS, 512,
            wk + (size_t)i*131072, wv + (size_t)i*131072, 512,
            bk + i*DIM, bv + i*DIM,
            kbuf, vbuf, 256, 8);

        ctx_part_kernel  <<<BB * NH * CCH, 1024>>>();
        ctx_reduce_kernel<<<BB * NH, 1024>>>(i);
    }

    qstats_part_kernel  <<<dim3(BB, QCH, 3), 256>>>();
    qstats_reduce_kernel<<<dim3(BB, 3), 256>>>();

    att_kernel<<<BB * (SEQ / 32), 384>>>();

    // out = cat @ Wrp + brp  (K'=768, N=256)
    gemm_mma<<<dim3(2, MTOT/128, 1), 256>>>(cbuf, cbuf, 1536, wf, wf, 1536,
                                            brp, brp, out, out, 256, 24);
}

// round 5
// speedup vs baseline: 1.9443x; 1.0247x over previous
#include <cuda_runtime.h>
#include <cuda_bf16.h>
#include <cstdint>

#define BB   4
#define SEQ  8192
#define DIM  256
#define NH   8
#define HD   32
#define MTOT (BB*SEQ)        // 32768
#define QCH  128             // q-stats chunks (64 rows each)
#define CCH  32

// ===================== scratch (device globals) =====================
__device__ __nv_bfloat16 g_a[7ull * MTOT * 512];     // activations hi|lo
__device__ __nv_bfloat16 g_c[(size_t)MTOT * 1536];   // concat hi|lo
__device__ __nv_bfloat16 g_w[1572864];               // wq|wk|wv|wf, transposed hi|lo
__device__ float g_qall[(size_t)MTOT * 768];
__device__ float g_kbuf[(size_t)MTOT * DIM];
__device__ float g_vbuf[(size_t)MTOT * DIM];
__device__ float g_ctx [BB * 24 * HD * HD];
__device__ float g_ctxp[BB * NH * CCH * HD * HD];
__device__ float g_qm  [BB * 768];
__device__ float g_qs  [BB * 768];                   // 1/sum
__device__ float g_qmp [BB * QCH * 768];
__device__ float g_qsp [BB * QCH * 768];

// ===================== helpers =====================
__device__ __forceinline__ uint32_t smem_u32(const void* p){
    uint32_t a;
    asm("{ .reg .u64 t; cvta.to.shared.u64 t, %1; cvt.u32.u64 %0, t; }" : "=r"(a) : "l"(p));
    return a;
}
__device__ __forceinline__ void cp16(uint32_t dst, const void* src){
    asm volatile("cp.async.cg.shared.global [%0], [%1], 16;" :: "r"(dst), "l"(src) : "memory");
}
__device__ __forceinline__ void cp_commit(){ asm volatile("cp.async.commit_group;" ::: "memory"); }
__device__ __forceinline__ void cp_wait1(){ asm volatile("cp.async.wait_group 1;" ::: "memory"); }
__device__ __forceinline__ void cp_wait0(){ asm volatile("cp.async.wait_group 0;" ::: "memory"); }

__device__ __forceinline__ void ldsm4(uint32_t& r0, uint32_t& r1, uint32_t& r2, uint32_t& r3, uint32_t addr){
    asm volatile("ldmatrix.sync.aligned.m8n8.x4.shared.b16 {%0,%1,%2,%3}, [%4];"
        : "=r"(r0), "=r"(r1), "=r"(r2), "=r"(r3) : "r"(addr));
}
__device__ __forceinline__ void mma16816(float* d, const uint32_t* a, const uint32_t* b){
    asm volatile("mma.sync.aligned.m16n8k16.row.col.f32.bf16.bf16.f32 "
        "{%0,%1,%2,%3}, {%4,%5,%6,%7}, {%8,%9}, {%0,%1,%2,%3};"
        : "+f"(d[0]), "+f"(d[1]), "+f"(d[2]), "+f"(d[3])
        : "r"(a[0]), "r"(a[1]), "r"(a[2]), "r"(a[3]), "r"(b[0]), "r"(b[1]));
}

// ===================== GEMM (warp-MMA, bf16x3 via K-remap, 3-stage ring) =====
// C[M,N] = A' @ B'^T + bias, K' = 3*KH*32, walked as [AhiBhi][AloBhi][AhiBlo].
#define STG_BYTES 20480
#define GEMM_SMEM (3 * STG_BYTES)

__global__ void __launch_bounds__(256, 2)
gemm_mma(const __nv_bfloat16* __restrict__ A0, const __nv_bfloat16* __restrict__ A1, int lda,
         const __nv_bfloat16* __restrict__ B0, const __nv_bfloat16* __restrict__ B1, int ldb,
         const float* __restrict__ bias0, const float* __restrict__ bias1,
         float* __restrict__ C0, float* __restrict__ C1, int N, int KH)
{
    extern __shared__ __align__(16) char smem[];
    const __nv_bfloat16* A = blockIdx.z ? A1 : A0;
    const __nv_bfloat16* B = blockIdx.z ? B1 : B0;
    const float* bias      = blockIdx.z ? bias1 : bias0;
    float* C               = blockIdx.z ? C1 : C0;

    const int tid  = threadIdx.x;
    const int lane = tid & 31, wid = tid >> 5;
    const int wm = wid >> 2, wn = wid & 3;            // warp grid 2x4
    const int row0 = blockIdx.y * 128;
    const int col0 = blockIdx.x * 128;
    const int nkc = 3 * KH;

    float acc[4][4][4];
#pragma unroll
    for (int i = 0; i < 4; i++)
#pragma unroll
        for (int j = 0; j < 4; j++)
#pragma unroll
            for (int v = 0; v < 4; v++) acc[i][j][v] = 0.f;

    const uint32_t smem_base = smem_u32(smem);
    const int ch0 = tid * 2;

    auto prefetch = [&](int kc) {
        int s = kc % 3;
        int a_k = (kc < 2 * KH) ? kc : kc - 2 * KH;   // hi, lo, hi
        int b_k = (kc < KH)     ? kc : kc - KH;       // hi, hi, lo
        uint32_t As = smem_base + s * STG_BYTES;
        uint32_t Bs = As + 10240;
#pragma unroll
        for (int t = 0; t < 2; t++) {
            int ch = ch0 + t;
            int r = ch >> 2, c = ch & 3;
            cp16(As + r * 80 + c * 16,
                 A + (size_t)(row0 + r) * lda + a_k * 32 + c * 8);
            cp16(Bs + r * 80 + c * 16,
                 B + (size_t)(col0 + r) * ldb + b_k * 32 + c * 8);
        }
        cp_commit();
    };

    prefetch(0);
    if (nkc > 1) prefetch(1);

    const int arow = lane & 15, acolh = (lane >> 4) * 8;
    const int bn   = (lane & 7) + (lane >> 4) * 8;
    const int bkh  = ((lane >> 3) & 1) * 8;

    for (int kc = 0; kc < nkc; kc++) {
        if (kc + 1 < nkc) cp_wait1(); else cp_wait0();
        __syncthreads();
        if (kc + 2 < nkc) prefetch(kc + 2);

        int s = kc % 3;
        uint32_t As = smem_base + s * STG_BYTES;
        uint32_t Bs = As + 10240;

#pragma unroll
        for (int kk = 0; kk < 32; kk += 16) {
            uint32_t af[4][4];
#pragma unroll
            for (int i = 0; i < 4; i++) {
                uint32_t addr = As + (wm * 64 + i * 16 + arow) * 80 + (kk + acolh) * 2;
                ldsm4(af[i][0], af[i][1], af[i][2], af[i][3], addr);
            }
            uint32_t bf[4][2];
#pragma unroll
            for (int jp = 0; jp < 2; jp++) {
                uint32_t addr = Bs + (wn * 32 + jp * 16 + bn) * 80 + (kk + bkh) * 2;
                ldsm4(bf[2*jp][0], bf[2*jp][1], bf[2*jp+1][0], bf[2*jp+1][1], addr);
            }
#pragma unroll
            for (int i = 0; i < 4; i++)
#pragma unroll
                for (int j = 0; j < 4; j++)
                    mma16816(acc[i][j], af[i], bf[j]);
        }
    }

    const int g = lane >> 2, tg = lane & 3;
    float2 bb[4];
#pragma unroll
    for (int j = 0; j < 4; j++) {
        int c = col0 + wn * 32 + j * 8 + 2 * tg;
        bb[j] = make_float2(bias[c], bias[c + 1]);
    }
#pragma unroll
    for (int i = 0; i < 4; i++) {
        int r = row0 + wm * 64 + i * 16 + g;
#pragma unroll
        for (int j = 0; j < 4; j++) {
            int c = col0 + wn * 32 + j * 8 + 2 * tg;
            *reinterpret_cast<float2*>(C + (size_t)r * N + c) =
                make_float2(acc[i][j][0] + bb[j].x, acc[i][j][1] + bb[j].y);
            *reinterpret_cast<float2*>(C + (size_t)(r + 8) * N + c) =
                make_float2(acc[i][j][2] + bb[j].x, acc[i][j][3] + bb[j].y);
        }
    }
}

// ===================== prep kernels =====================
__device__ __forceinline__ void split4(float4 x, uint2& H, uint2& L)
{
    __nv_bfloat16 h0 = __float2bfloat16(x.x), h1 = __float2bfloat16(x.y);
    __nv_bfloat16 h2 = __float2bfloat16(x.z), h3 = __float2bfloat16(x.w);
    __nv_bfloat16 l0 = __float2bfloat16(x.x - __bfloat162float(h0));
    __nv_bfloat16 l1 = __float2bfloat16(x.y - __bfloat162float(h1));
    __nv_bfloat16 l2 = __float2bfloat16(x.z - __bfloat162float(h2));
    __nv_bfloat16 l3 = __float2bfloat16(x.w - __bfloat162float(h3));
    union { __nv_bfloat162 b2[2]; uint2 u; } HH, LL;
    HH.b2[0] = __nv_bfloat162(h0, h1); HH.b2[1] = __nv_bfloat162(h2, h3);
    LL.b2[0] = __nv_bfloat162(l0, l1); LL.b2[1] = __nv_bfloat162(l2, l3);
    H = HH.u; L = LL.u;
}

__global__ void __launch_bounds__(256)
prep_q(const float* __restrict__ a, const float* __restrict__ b,
       __nv_bfloat16* __restrict__ o, int n4)
{
    int i = blockIdx.x * 256 + threadIdx.x;
    if (i >= n4) return;
    float4 x = reinterpret_cast<const float4*>(a)[i];
    float4 y = reinterpret_cast<const float4*>(b)[i];
    x.x += y.x; x.y += y.y; x.z += y.z; x.w += y.w;
    uint2 H, L; split4(x, H, L);
    int row = i >> 6, cu = i & 63;
    reinterpret_cast<uint2*>(o)[row * 128 + cu]      = H;
    reinterpret_cast<uint2*>(o)[row * 128 + 64 + cu] = L;
}

__global__ void __launch_bounds__(256)
prep_kv(const float* __restrict__ f, const float* __restrict__ pe,
        __nv_bfloat16* __restrict__ ok, __nv_bfloat16* __restrict__ ov, int n4)
{
    int i = blockIdx.x * 256 + threadIdx.x;
    if (i >= n4) return;
    float4 x = reinterpret_cast<const float4*>(f)[i];
    float4 y = reinterpret_cast<const float4*>(pe)[i];
    float4 k = make_float4(x.x + y.x, x.y + y.y, x.z + y.z, x.w + y.w);
    uint2 H, L;
    int row = i >> 6, cu = i & 63;
    split4(k, H, L);
    reinterpret_cast<uint2*>(ok)[row * 128 + cu]      = H;
    reinterpret_cast<uint2*>(ok)[row * 128 + 64 + cu] = L;
    split4(x, H, L);
    reinterpret_cast<uint2*>(ov)[row * 128 + cu]      = H;
    reinterpret_cast<uint2*>(ov)[row * 128 + 64 + cu] = L;
}

// all weights in ONE launch: wq(3x 256x512) | wk(3x) | wv(3x) | wf(256x1536)
__global__ void __launch_bounds__(256)
prep_w_all(const float* __restrict__ Wq, const float* __restrict__ Wk,
           const float* __restrict__ Wv, const float* __restrict__ Wrp,
           __nv_bfloat16* __restrict__ o)
{
    int t = blockIdx.x * 256 + threadIdx.x;      // 0..786431
    if (t < 589824) {
        int mat = t >> 16, idx = t & 65535;
        int n = idx >> 8, k = idx & 255;
        const float* W = (mat < 3) ? Wq + (size_t)mat * 65536
                       : (mat < 6) ? Wk + (size_t)(mat - 3) * 65536
                                   : Wv + (size_t)(mat - 6) * 65536;
        float x = W[k * 256 + n];
        size_t ob = (size_t)mat * 131072 + (size_t)n * 512 + k;
        __nv_bfloat16 h = __float2bfloat16(x);
        o[ob]       = h;
        o[ob + 256] = __float2bfloat16(x - __bfloat162float(h));
    } else {
        int idx = t - 589824;
        int n = idx / 768, k = idx - n * 768;
        float x = Wrp[(size_t)k * 256 + n];
        size_t ob = 1179648 + (size_t)n * 1536 + k;
        __nv_bfloat16 h = __float2bfloat16(x);
        o[ob]       = h;
        o[ob + 768] = __float2bfloat16(x - __bfloat162float(h));
    }
}

// ===================== q softmax stats over sequence axis (768 ch) ==========
__global__ void qstats_part_kernel()
{
    int b = blockIdx.x, ch = blockIdx.y, c = blockIdx.z * 256 + threadIdx.x;
    const int ROWS = SEQ / QCH;                       // 64
    const float* p = g_qall + ((size_t)b * SEQ + (size_t)ch * ROWS) * 768 + c;
    float m0=-1e30f,m1=-1e30f,m2=-1e30f,m3=-1e30f, s0=0.f,s1=0.f,s2=0.f,s3=0.f;
    for (int r = 0; r < ROWS; r += 4) {
        float x0 = p[(size_t)(r+0)*768], x1 = p[(size_t)(r+1)*768];
        float x2 = p[(size_t)(r+2)*768], x3 = p[(size_t)(r+3)*768];
        float nm;
        nm = fmaxf(m0,x0); s0 = s0*__expf(m0-nm)+__expf(x0-nm); m0 = nm;
        nm = fmaxf(m1,x1); s1 = s1*__expf(m1-nm)+__expf(x1-nm); m1 = nm;
        nm = fmaxf(m2,x2); s2 = s2*__expf(m2-nm)+__expf(x2-nm); m2 = nm;
        nm = fmaxf(m3,x3); s3 = s3*__expf(m3-nm)+__expf(x3-nm); m3 = nm;
    }
    float m = fmaxf(fmaxf(m0,m1), fmaxf(m2,m3));
    float s = s0*__expf(m0-m) + s1*__expf(m1-m) + s2*__expf(m2-m) + s3*__expf(m3-m);
    g_qmp[((size_t)b*QCH+ch)*768 + c] = m;
    g_qsp[((size_t)b*QCH+ch)*768 + c] = s;
}

__global__ void qstats_reduce_kernel()
{
    int b = blockIdx.x, c = blockIdx.y * 256 + threadIdx.x;
    float m = -1e30f;
    for (int ch = 0; ch < QCH; ch++) m = fmaxf(m, g_qmp[((size_t)b*QCH+ch)*768 + c]);
    float s = 0.f;
    for (int ch = 0; ch < QCH; ch++)
        s += g_qsp[((size_t)b*QCH+ch)*768 + c] * __expf(g_qmp[((size_t)b*QCH+ch)*768 + c] - m);
    g_qm[b*768 + c] = m;
    g_qs[b*768 + c] = 1.f / s;
}

// ===================== ctx = softmax_c(k)^T v (per branch) =====================
__global__ void __launch_bounds__(1024)
ctx_part_kernel()
{
    int blk = blockIdx.x;
    int chunk = blk & (CCH-1), hh = (blk>>5) & (NH-1), b = blk >> 8;
    int tid = threadIdx.x;
    int r = tid >> 5, col = tid & 31;
    int c = r, d = col;
    __shared__ float ks[2][32][33];
    __shared__ float vs[2][32][33];
    float acc = 0.f;
    const size_t base = ((size_t)b*SEQ + (size_t)chunk*(SEQ/CCH))*DIM + hh*HD;
    for (int t = 0; t < (SEQ/CCH)/32; t++) {
        float kv = g_kbuf[base + (size_t)(t*32+r)*DIM + col];
        float vv = g_vbuf[base + (size_t)(t*32+r)*DIM + col];
        float mx = kv;
        #pragma unroll
        for (int o = 16; o; o >>= 1) mx = fmaxf(mx, __shfl_xor_sync(0xffffffffu, mx, o));
        float e = __expf(kv - mx);
        float sm = e;
        #pragma unroll
        for (int o = 16; o; o >>= 1) sm += __shfl_xor_sync(0xffffffffu, sm, o);
        int bufi = t & 1;
        ks[bufi][r][col] = e / sm;
        vs[bufi][r][col] = vv;
        __syncthreads();
        #pragma unroll
        for (int rr = 0; rr < 32; rr++) acc += ks[bufi][rr][c] * vs[bufi][rr][d];
    }
    g_ctxp[(size_t)blk*(HD*HD) + tid] = acc;
}

__global__ void __launch_bounds__(1024)
ctx_reduce_kernel(int branch)
{
    int bh = blockIdx.x, tid = threadIdx.x;
    int b = bh >> 3, h = bh & 7;
    float s = 0.f;
    for (int ch = 0; ch < CCH; ch++)
        s += g_ctxp[((size_t)bh*CCH+ch)*(HD*HD) + tid];
    g_ctx[((size_t)b*24 + branch*8 + h)*(HD*HD) + tid] = s;
}

// ===================== attend: all 3 branches, ctx in registers ==============
__global__ void __launch_bounds__(384, 1)
att_kernel()
{
    __shared__ float sq_s[8][768];
    __shared__ float qm_s[768];
    __shared__ float qi_s[768];

    int blk = blockIdx.x;
    int b   = blk / (SEQ/32);
    int n0  = (blk % (SEQ/32)) * 32;
    int tid = threadIdx.x;
    int ch0 = tid * 2;
    int h24 = ch0 >> 5;
    int d0  = ch0 & 31;

    float cr[32][2];
    const float* cp = g_ctx + ((size_t)b*24 + h24) * (HD*HD) + d0;
    #pragma unroll
    for (int c = 0; c < 32; c++) {
        float2 v = *reinterpret_cast<const float2*>(cp + c*32);
        cr[c][0] = v.x; cr[c][1] = v.y;
    }
    {
        float2 m2 = *reinterpret_cast<const float2*>(g_qm + b*768 + ch0);
        float2 i2 = *reinterpret_cast<const float2*>(g_qs + b*768 + ch0);
        qm_s[ch0] = m2.x; qm_s[ch0+1] = m2.y;
        qi_s[ch0] = i2.x; qi_s[ch0+1] = i2.y;
    }
    __syncthreads();

    const float* qrow = g_qall + ((size_t)b*SEQ + n0) * 768;
    __nv_bfloat16* orow = g_c + ((size_t)b*SEQ + n0) * 1536;

    for (int chunk = 0; chunk < 4; chunk++) {
        #pragma unroll
        for (int v = 0; v < 4; v++) {
            int idx = v * 384 + tid;
            int r = idx / 192, col = (idx - r * 192) * 4;
            float4 x = *reinterpret_cast<const float4*>(qrow + (size_t)(chunk*8 + r)*768 + col);
            float4 m = *reinterpret_cast<const float4*>(qm_s + col);
            float4 iv = *reinterpret_cast<const float4*>(qi_s + col);
            float4 sq = make_float4(__expf(x.x - m.x) * iv.x, __expf(x.y - m.y) * iv.y,
                                    __expf(x.z - m.z) * iv.z, __expf(x.w - m.w) * iv.w);
            *reinterpret_cast<float4*>(&sq_s[r][col]) = sq;
        }
        __syncthreads();

        #pragma unroll
        for (int n = 0; n < 8; n++) {
            float4 s4[8];
            const float4* sp = reinterpret_cast<const float4*>(&sq_s[n][h24 * 32]);
            #pragma unroll
            for (int u = 0; u < 8; u++) s4[u] = sp[u];
            const float* s = reinterpret_cast<const float*>(s4);
            float a0 = 0.f, a1 = 0.f;
            #pragma unroll
            for (int c = 0; c < 32; c++) { a0 += cr[c][0] * s[c]; a1 += cr[c][1] * s[c]; }

            size_t ro = (size_t)(chunk*8 + n) * 1536;
            __nv_bfloat16 h0 = __float2bfloat16(a0);
            __nv_bfloat16 h1 = __float2bfloat16(a1);
            __nv_bfloat16 l0 = __float2bfloat16(a0 - __bfloat162float(h0));
            __nv_bfloat16 l1 = __float2bfloat16(a1 - __bfloat162float(h1));
            *reinterpret_cast<__nv_bfloat162*>(orow + ro + ch0)       = __nv_bfloat162(h0, h1);
            *reinterpret_cast<__nv_bfloat162*>(orow + ro + 768 + ch0) = __nv_bfloat162(l0, l1);
        }
        __syncthreads();
    }
}

// ===================== launcher =====================
extern "C" void kernel_launch(void* const* d_in, const int* in_sizes, int n_in,
                              void* d_out, int out_size)
{
    const float* f[4]   = {(const float*)d_in[0], (const float*)d_in[1],
                           (const float*)d_in[2], (const float*)d_in[3]};
    const float* fpe[4] = {(const float*)d_in[4], (const float*)d_in[5],
                           (const float*)d_in[6], (const float*)d_in[7]};
    const float* Wq  = (const float*)d_in[8];
    const float* bq  = (const float*)d_in[9];
    const float* Wk  = (const float*)d_in[10];
    const float* bk  = (const float*)d_in[11];
    const float* Wv  = (const float*)d_in[12];
    const float* bv  = (const float*)d_in[13];
    const float* Wrp = (const float*)d_in[14];
    const float* brp = (const float*)d_in[15];
    float* out = (float*)d_out;

    cudaFuncSetAttribute(gemm_mma, cudaFuncAttributeMaxDynamicSharedMemorySize, GEMM_SMEM);

    float *qall, *kbuf, *vbuf;
    __nv_bfloat16 *abuf, *cbuf, *wbuf;
    cudaGetSymbolAddress((void**)&qall, g_qall);
    cudaGetSymbolAddress((void**)&kbuf, g_kbuf);
    cudaGetSymbolAddress((void**)&vbuf, g_vbuf);
    cudaGetSymbolAddress((void**)&abuf, g_a);
    cudaGetSymbolAddress((void**)&cbuf, g_c);
    cudaGetSymbolAddress((void**)&wbuf, g_w);

    const size_t AS = (size_t)MTOT * 512;
    const int n4 = MTOT * DIM / 4;
    const int pb = n4 / 256;

    __nv_bfloat16* wq = wbuf;                    // 3 x (256 x 512)
    __nv_bfloat16* wk = wbuf + 393216;
    __nv_bfloat16* wv = wbuf + 786432;
    __nv_bfloat16* wf = wbuf + 1179648;          // 256 x 1536

    // launches 1..5 (ncu profiles launch #6 = qall GEMM)
    prep_q<<<pb, 256>>>(f[0], fpe[0], abuf, n4);
    for (int i = 1; i <= 3; i++)
        prep_kv<<<pb, 256>>>(f[i], fpe[i], abuf + i * AS, abuf + (3 + i) * AS, n4);
    prep_w_all<<<3072, 256>>>(Wq, Wk, Wv, Wrp, wbuf);

    // launch 6: qall = q_in @ [Wq0|Wq1|Wq2]  (N=768)
    gemm_mma<<<dim3(6, MTOT/128, 1), 256, GEMM_SMEM>>>(abuf, abuf, 512, wq, wq, 512,
                                                       bq, bq, qall, qall, 768, 8);

    for (int i = 0; i < 3; i++) {
        gemm_mma<<<dim3(2, MTOT/128, 2), 256, GEMM_SMEM>>>(
            abuf + (1+i)*AS, abuf + (4+i)*AS, 512,
            wk + (size_t)i*131072, wv + (size_t)i*131072, 512,
            bk + i*DIM, bv + i*DIM,
            kbuf, vbuf, 256, 8);

        ctx_part_kernel  <<<BB * NH * CCH, 1024>>>();
        ctx_reduce_kernel<<<BB * NH, 1024>>>(i);
    }

    qstats_part_kernel  <<<dim3(BB, QCH, 3), 256>>>();
    qstats_reduce_kernel<<<dim3(BB, 3), 256>>>();

    att_kernel<<<BB * (SEQ / 32), 384>>>();

    gemm_mma<<<dim3(2, MTOT/128, 1), 256, GEMM_SMEM>>>(cbuf, cbuf, 1536, wf, wf, 1536,
                                                       brp, brp, out, out, 256, 24);
}

// round 6
// speedup vs baseline: 3.1022x; 1.5955x over previous
#include <cuda_runtime.h>
#include <cuda_fp16.h>
#include <cstdint>

#define BB   4
#define SEQ  8192
#define DIM  256
#define NH   8
#define HD   32
#define MTOT (BB*SEQ)        // 32768
#define QCH  128             // q-stats chunks (64 rows each)
#define CCH  32

// ===================== scratch (device globals) =====================
__device__ __half g_a[7ull * MTOT * 256];        // fp16 activations: q_in, k2..k4, v2..v4
__device__ __half g_c[(size_t)MTOT * 768];       // fp16 concat buffer
__device__ __half g_w[786432];                   // fp16 weights: wq(768x256)|wk,wv(6x256x256)|wf(256x768)
__device__ float g_qall[(size_t)MTOT * 768];
__device__ float g_kbuf[(size_t)MTOT * DIM];
__device__ float g_vbuf[(size_t)MTOT * DIM];
__device__ float g_ctx [BB * 24 * HD * HD];
__device__ float g_ctxp[BB * NH * CCH * HD * HD];
__device__ float g_qm  [BB * 768];
__device__ float g_qs  [BB * 768];               // 1/sum
__device__ float g_qmp [BB * QCH * 768];
__device__ float g_qsp [BB * QCH * 768];

// ===================== helpers =====================
__device__ __forceinline__ uint32_t smem_u32(const void* p){
    uint32_t a;
    asm("{ .reg .u64 t; cvta.to.shared.u64 t, %1; cvt.u32.u64 %0, t; }" : "=r"(a) : "l"(p));
    return a;
}
__device__ __forceinline__ void cp16(uint32_t dst, const void* src){
    asm volatile("cp.async.cg.shared.global [%0], [%1], 16;" :: "r"(dst), "l"(src) : "memory");
}
__device__ __forceinline__ void cp_commit(){ asm volatile("cp.async.commit_group;" ::: "memory"); }
__device__ __forceinline__ void cp_wait1(){ asm volatile("cp.async.wait_group 1;" ::: "memory"); }
__device__ __forceinline__ void cp_wait0(){ asm volatile("cp.async.wait_group 0;" ::: "memory"); }

__device__ __forceinline__ void ldsm4(uint32_t& r0, uint32_t& r1, uint32_t& r2, uint32_t& r3, uint32_t addr){
    asm volatile("ldmatrix.sync.aligned.m8n8.x4.shared.b16 {%0,%1,%2,%3}, [%4];"
        : "=r"(r0), "=r"(r1), "=r"(r2), "=r"(r3) : "r"(addr));
}
__device__ __forceinline__ void mma16816(float* d, const uint32_t* a, const uint32_t* b){
    asm volatile("mma.sync.aligned.m16n8k16.row.col.f32.f16.f16.f32 "
        "{%0,%1,%2,%3}, {%4,%5,%6,%7}, {%8,%9}, {%0,%1,%2,%3};"
        : "+f"(d[0]), "+f"(d[1]), "+f"(d[2]), "+f"(d[3])
        : "r"(a[0]), "r"(a[1]), "r"(a[2]), "r"(a[3]), "r"(b[0]), "r"(b[1]));
}

// ===================== GEMM (warp-MMA fp16, 3-stage cp.async ring) ==========
// C[M,N] = A[M,K] @ B[N,K]^T + bias. K = KH*32.
#define STG_BYTES 20480
#define GEMM_SMEM (3 * STG_BYTES)

__global__ void __launch_bounds__(256, 2)
gemm_mma(const __half* __restrict__ A0, const __half* __restrict__ A1, int lda,
         const __half* __restrict__ B0, const __half* __restrict__ B1, int ldb,
         const float* __restrict__ bias0, const float* __restrict__ bias1,
         float* __restrict__ C0, float* __restrict__ C1, int N, int KH)
{
    extern __shared__ __align__(16) char smem[];
    const __half* A   = blockIdx.z ? A1 : A0;
    const __half* B   = blockIdx.z ? B1 : B0;
    const float* bias = blockIdx.z ? bias1 : bias0;
    float* C          = blockIdx.z ? C1 : C0;

    const int tid  = threadIdx.x;
    const int lane = tid & 31, wid = tid >> 5;
    const int wm = wid >> 2, wn = wid & 3;            // warp grid 2x4
    const int row0 = blockIdx.y * 128;
    const int col0 = blockIdx.x * 128;
    const int nkc = KH;

    float acc[4][4][4];
#pragma unroll
    for (int i = 0; i < 4; i++)
#pragma unroll
        for (int j = 0; j < 4; j++)
#pragma unroll
            for (int v = 0; v < 4; v++) acc[i][j][v] = 0.f;

    const uint32_t smem_base = smem_u32(smem);
    const int ch0 = tid * 2;

    auto prefetch = [&](int kc) {
        int s = kc % 3;
        uint32_t As = smem_base + s * STG_BYTES;
        uint32_t Bs = As + 10240;
#pragma unroll
        for (int t = 0; t < 2; t++) {
            int ch = ch0 + t;
            int r = ch >> 2, c = ch & 3;
            cp16(As + r * 80 + c * 16,
                 A + (size_t)(row0 + r) * lda + kc * 32 + c * 8);
            cp16(Bs + r * 80 + c * 16,
                 B + (size_t)(col0 + r) * ldb + kc * 32 + c * 8);
        }
        cp_commit();
    };

    prefetch(0);
    if (nkc > 1) prefetch(1);

    const int arow = lane & 15, acolh = (lane >> 4) * 8;
    const int bn   = (lane & 7) + (lane >> 4) * 8;
    const int bkh  = ((lane >> 3) & 1) * 8;

    for (int kc = 0; kc < nkc; kc++) {
        if (kc + 1 < nkc) cp_wait1(); else cp_wait0();
        __syncthreads();
        if (kc + 2 < nkc) prefetch(kc + 2);

        int s = kc % 3;
        uint32_t As = smem_base + s * STG_BYTES;
        uint32_t Bs = As + 10240;

#pragma unroll
        for (int kk = 0; kk < 32; kk += 16) {
            uint32_t af[4][4];
#pragma unroll
            for (int i = 0; i < 4; i++) {
                uint32_t addr = As + (wm * 64 + i * 16 + arow) * 80 + (kk + acolh) * 2;
                ldsm4(af[i][0], af[i][1], af[i][2], af[i][3], addr);
            }
            uint32_t bf[4][2];
#pragma unroll
            for (int jp = 0; jp < 2; jp++) {
                uint32_t addr = Bs + (wn * 32 + jp * 16 + bn) * 80 + (kk + bkh) * 2;
                ldsm4(bf[2*jp][0], bf[2*jp][1], bf[2*jp+1][0], bf[2*jp+1][1], addr);
            }
#pragma unroll
            for (int i = 0; i < 4; i++)
#pragma unroll
                for (int j = 0; j < 4; j++)
                    mma16816(acc[i][j], af[i], bf[j]);
        }
    }

    const int g = lane >> 2, tg = lane & 3;
    float2 bb[4];
#pragma unroll
    for (int j = 0; j < 4; j++) {
        int c = col0 + wn * 32 + j * 8 + 2 * tg;
        bb[j] = make_float2(bias[c], bias[c + 1]);
    }
#pragma unroll
    for (int i = 0; i < 4; i++) {
        int r = row0 + wm * 64 + i * 16 + g;
#pragma unroll
        for (int j = 0; j < 4; j++) {
            int c = col0 + wn * 32 + j * 8 + 2 * tg;
            *reinterpret_cast<float2*>(C + (size_t)r * N + c) =
                make_float2(acc[i][j][0] + bb[j].x, acc[i][j][1] + bb[j].y);
            *reinterpret_cast<float2*>(C + (size_t)(r + 8) * N + c) =
                make_float2(acc[i][j][2] + bb[j].x, acc[i][j][3] + bb[j].y);
        }
    }
}

// ===================== prep kernels =====================
__device__ __forceinline__ uint2 cvt4(float4 x)
{
    union { __half2 h2[2]; uint2 u; } U;
    U.h2[0] = __floats2half2_rn(x.x, x.y);
    U.h2[1] = __floats2half2_rn(x.z, x.w);
    return U.u;
}

__global__ void __launch_bounds__(256)
prep_q(const float* __restrict__ a, const float* __restrict__ b,
       __half* __restrict__ o, int n4)
{
    int i = blockIdx.x * 256 + threadIdx.x;
    if (i >= n4) return;
    float4 x = reinterpret_cast<const float4*>(a)[i];
    float4 y = reinterpret_cast<const float4*>(b)[i];
    x.x += y.x; x.y += y.y; x.z += y.z; x.w += y.w;
    reinterpret_cast<uint2*>(o)[i] = cvt4(x);
}

__global__ void __launch_bounds__(256)
prep_kv(const float* __restrict__ f, const float* __restrict__ pe,
        __half* __restrict__ ok, __half* __restrict__ ov, int n4)
{
    int i = blockIdx.x * 256 + threadIdx.x;
    if (i >= n4) return;
    float4 x = reinterpret_cast<const float4*>(f)[i];
    float4 y = reinterpret_cast<const float4*>(pe)[i];
    float4 k = make_float4(x.x + y.x, x.y + y.y, x.z + y.z, x.w + y.w);
    reinterpret_cast<uint2*>(ok)[i] = cvt4(k);
    reinterpret_cast<uint2*>(ov)[i] = cvt4(x);
}

// all weights, transposed, fp16: wq[768][256] | wk 3x[256][256] | wv 3x | wf[256][768]
__global__ void __launch_bounds__(256)
prep_w_all(const float* __restrict__ Wq, const float* __restrict__ Wk,
           const float* __restrict__ Wv, const float* __restrict__ Wrp,
           __half* __restrict__ o)
{
    int t = blockIdx.x * 256 + threadIdx.x;      // 0..786431
    if (t < 589824) {
        int mat = t >> 16, idx = t & 65535;
        int n = idx >> 8, k = idx & 255;
        const float* W = (mat < 3) ? Wq + (size_t)mat * 65536
                       : (mat < 6) ? Wk + (size_t)(mat - 3) * 65536
                                   : Wv + (size_t)(mat - 6) * 65536;
        o[(size_t)mat * 65536 + (size_t)n * 256 + k] = __float2half_rn(W[k * 256 + n]);
    } else {
        int idx = t - 589824;
        int n = idx / 768, k = idx - n * 768;
        o[589824 + (size_t)n * 768 + k] = __float2half_rn(Wrp[(size_t)k * 256 + n]);
    }
}

// ===================== q softmax stats over sequence axis (768 ch) ==========
__global__ void qstats_part_kernel()
{
    int b = blockIdx.x, ch = blockIdx.y, c = blockIdx.z * 256 + threadIdx.x;
    const int ROWS = SEQ / QCH;                       // 64
    const float* p = g_qall + ((size_t)b * SEQ + (size_t)ch * ROWS) * 768 + c;
    float m0=-1e30f,m1=-1e30f,m2=-1e30f,m3=-1e30f, s0=0.f,s1=0.f,s2=0.f,s3=0.f;
    for (int r = 0; r < ROWS; r += 4) {
        float x0 = p[(size_t)(r+0)*768], x1 = p[(size_t)(r+1)*768];
        float x2 = p[(size_t)(r+2)*768], x3 = p[(size_t)(r+3)*768];
        float nm;
        nm = fmaxf(m0,x0); s0 = s0*__expf(m0-nm)+__expf(x0-nm); m0 = nm;
        nm = fmaxf(m1,x1); s1 = s1*__expf(m1-nm)+__expf(x1-nm); m1 = nm;
        nm = fmaxf(m2,x2); s2 = s2*__expf(m2-nm)+__expf(x2-nm); m2 = nm;
        nm = fmaxf(m3,x3); s3 = s3*__expf(m3-nm)+__expf(x3-nm); m3 = nm;
    }
    float m = fmaxf(fmaxf(m0,m1), fmaxf(m2,m3));
    float s = s0*__expf(m0-m) + s1*__expf(m1-m) + s2*__expf(m2-m) + s3*__expf(m3-m);
    g_qmp[((size_t)b*QCH+ch)*768 + c] = m;
    g_qsp[((size_t)b*QCH+ch)*768 + c] = s;
}

__global__ void qstats_reduce_kernel()
{
    int b = blockIdx.x, c = blockIdx.y * 256 + threadIdx.x;
    float m = -1e30f;
    for (int ch = 0; ch < QCH; ch++) m = fmaxf(m, g_qmp[((size_t)b*QCH+ch)*768 + c]);
    float s = 0.f;
    for (int ch = 0; ch < QCH; ch++)
        s += g_qsp[((size_t)b*QCH+ch)*768 + c] * __expf(g_qmp[((size_t)b*QCH+ch)*768 + c] - m);
    g_qm[b*768 + c] = m;
    g_qs[b*768 + c] = 1.f / s;
}

// ===================== ctx = softmax_c(k)^T v (per branch) =====================
__global__ void __launch_bounds__(1024)
ctx_part_kernel()
{
    int blk = blockIdx.x;
    int chunk = blk & (CCH-1), hh = (blk>>5) & (NH-1), b = blk >> 8;
    int tid = threadIdx.x;
    int r = tid >> 5, col = tid & 31;
    int c = r, d = col;
    __shared__ float ks[2][32][33];
    __shared__ float vs[2][32][33];
    float acc = 0.f;
    const size_t base = ((size_t)b*SEQ + (size_t)chunk*(SEQ/CCH))*DIM + hh*HD;
    for (int t = 0; t < (SEQ/CCH)/32; t++) {
        float kv = g_kbuf[base + (size_t)(t*32+r)*DIM + col];
        float vv = g_vbuf[base + (size_t)(t*32+r)*DIM + col];
        float mx = kv;
        #pragma unroll
        for (int o = 16; o; o >>= 1) mx = fmaxf(mx, __shfl_xor_sync(0xffffffffu, mx, o));
        float e = __expf(kv - mx);
        float sm = e;
        #pragma unroll
        for (int o = 16; o; o >>= 1) sm += __shfl_xor_sync(0xffffffffu, sm, o);
        int bufi = t & 1;
        ks[bufi][r][col] = e / sm;
        vs[bufi][r][col] = vv;
        __syncthreads();
        #pragma unroll
        for (int rr = 0; rr < 32; rr++) acc += ks[bufi][rr][c] * vs[bufi][rr][d];
    }
    g_ctxp[(size_t)blk*(HD*HD) + tid] = acc;
}

__global__ void __launch_bounds__(1024)
ctx_reduce_kernel(int branch)
{
    int bh = blockIdx.x, tid = threadIdx.x;
    int b = bh >> 3, h = bh & 7;
    float s = 0.f;
    for (int ch = 0; ch < CCH; ch++)
        s += g_ctxp[((size_t)bh*CCH+ch)*(HD*HD) + tid];
    g_ctx[((size_t)b*24 + branch*8 + h)*(HD*HD) + tid] = s;
}

// ===================== attend: all 3 branches, ctx in registers ==============
__global__ void __launch_bounds__(384, 1)
att_kernel()
{
    __shared__ float sq_s[8][768];
    __shared__ float qm_s[768];
    __shared__ float qi_s[768];

    int blk = blockIdx.x;
    int b   = blk / (SEQ/32);
    int n0  = (blk % (SEQ/32)) * 32;
    int tid = threadIdx.x;
    int ch0 = tid * 2;
    int h24 = ch0 >> 5;
    int d0  = ch0 & 31;

    float cr[32][2];
    const float* cp = g_ctx + ((size_t)b*24 + h24) * (HD*HD) + d0;
    #pragma unroll
    for (int c = 0; c < 32; c++) {
        float2 v = *reinterpret_cast<const float2*>(cp + c*32);
        cr[c][0] = v.x; cr[c][1] = v.y;
    }
    {
        float2 m2 = *reinterpret_cast<const float2*>(g_qm + b*768 + ch0);
        float2 i2 = *reinterpret_cast<const float2*>(g_qs + b*768 + ch0);
        qm_s[ch0] = m2.x; qm_s[ch0+1] = m2.y;
        qi_s[ch0] = i2.x; qi_s[ch0+1] = i2.y;
    }
    __syncthreads();

    const float* qrow = g_qall + ((size_t)b*SEQ + n0) * 768;
    __half* orow = g_c + ((size_t)b*SEQ + n0) * 768;

    for (int chunk = 0; chunk < 4; chunk++) {
        #pragma unroll
        for (int v = 0; v < 4; v++) {
            int idx = v * 384 + tid;
            int r = idx / 192, col = (idx - r * 192) * 4;
            float4 x = *reinterpret_cast<const float4*>(qrow + (size_t)(chunk*8 + r)*768 + col);
            float4 m = *reinterpret_cast<const float4*>(qm_s + col);
            float4 iv = *reinterpret_cast<const float4*>(qi_s + col);
            float4 sq = make_float4(__expf(x.x - m.x) * iv.x, __expf(x.y - m.y) * iv.y,
                                    __expf(x.z - m.z) * iv.z, __expf(x.w - m.w) * iv.w);
            *reinterpret_cast<float4*>(&sq_s[r][col]) = sq;
        }
        __syncthreads();

        #pragma unroll
        for (int n = 0; n < 8; n++) {
            float4 s4[8];
            const float4* sp = reinterpret_cast<const float4*>(&sq_s[n][h24 * 32]);
            #pragma unroll
            for (int u = 0; u < 8; u++) s4[u] = sp[u];
            const float* s = reinterpret_cast<const float*>(s4);
            float a0 = 0.f, a1 = 0.f;
            #pragma unroll
            for (int c = 0; c < 32; c++) { a0 += cr[c][0] * s[c]; a1 += cr[c][1] * s[c]; }

            *reinterpret_cast<__half2*>(orow + (size_t)(chunk*8 + n) * 768 + ch0) =
                __floats2half2_rn(a0, a1);
        }
        __syncthreads();
    }
}

// ===================== launcher =====================
extern "C" void kernel_launch(void* const* d_in, const int* in_sizes, int n_in,
                              void* d_out, int out_size)
{
    const float* f[4]   = {(const float*)d_in[0], (const float*)d_in[1],
                           (const float*)d_in[2], (const float*)d_in[3]};
    const float* fpe[4] = {(const float*)d_in[4], (const float*)d_in[5],
                           (const float*)d_in[6], (const float*)d_in[7]};
    const float* Wq  = (const float*)d_in[8];
    const float* bq  = (const float*)d_in[9];
    const float* Wk  = (const float*)d_in[10];
    const float* bk  = (const float*)d_in[11];
    const float* Wv  = (const float*)d_in[12];
    const float* bv  = (const float*)d_in[13];
    const float* Wrp = (const float*)d_in[14];
    const float* brp = (const float*)d_in[15];
    float* out = (float*)d_out;

    cudaFuncSetAttribute(gemm_mma, cudaFuncAttributeMaxDynamicSharedMemorySize, GEMM_SMEM);

    float *qall, *kbuf, *vbuf;
    __half *abuf, *cbuf, *wbuf;
    cudaGetSymbolAddress((void**)&qall, g_qall);
    cudaGetSymbolAddress((void**)&kbuf, g_kbuf);
    cudaGetSymbolAddress((void**)&vbuf, g_vbuf);
    cudaGetSymbolAddress((void**)&abuf, g_a);
    cudaGetSymbolAddress((void**)&cbuf, g_c);
    cudaGetSymbolAddress((void**)&wbuf, g_w);

    const size_t AS = (size_t)MTOT * 256;        // fp16 elems per activation slot
    const int n4 = MTOT * DIM / 4;
    const int pb = n4 / 256;

    __half* wq = wbuf;                    // [768][256]
    __half* wk = wbuf + 196608;           // 3 x [256][256]
    __half* wv = wbuf + 393216;
    __half* wf = wbuf + 589824;           // [256][768]

    // launches 1,2: inputs for the qall GEMM; launch 3 = GEMM (for ncu slot)
    prep_q<<<pb, 256>>>(f[0], fpe[0], abuf, n4);
    prep_w_all<<<3072, 256>>>(Wq, Wk, Wv, Wrp, wbuf);

    // qall = q_in @ [Wq0|Wq1|Wq2]  (N=768, K=256)
    gemm_mma<<<dim3(6, MTOT/128, 1), 256, GEMM_SMEM>>>(abuf, abuf, 256, wq, wq, 256,
                                                       bq, bq, qall, qall, 768, 8);

    for (int i = 1; i <= 3; i++)
        prep_kv<<<pb, 256>>>(f[i], fpe[i], abuf + i * AS, abuf + (3 + i) * AS, n4);

    for (int i = 0; i < 3; i++) {
        gemm_mma<<<dim3(2, MTOT/128, 2), 256, GEMM_SMEM>>>(
            abuf + (1+i)*AS, abuf + (4+i)*AS, 256,
            wk + (size_t)i*65536, wv + (size_t)i*65536, 256,
            bk + i*DIM, bv + i*DIM,
            kbuf, vbuf, 256, 8);

        ctx_part_kernel  <<<BB * NH * CCH, 1024>>>();
        ctx_reduce_kernel<<<BB * NH, 1024>>>(i);
    }

    qstats_part_kernel  <<<dim3(BB, QCH, 3), 256>>>();
    qstats_reduce_kernel<<<dim3(BB, 3), 256>>>();

    att_kernel<<<BB * (SEQ / 32), 384>>>();

    // out = cat @ Wrp + brp  (K=768, N=256)
    gemm_mma<<<dim3(2, MTOT/128, 1), 256, GEMM_SMEM>>>(cbuf, cbuf, 768, wf, wf, 768,
                                                       brp, brp, out, out, 256, 24);
}

// round 7
// speedup vs baseline: 4.4393x; 1.4310x over previous
#include <cuda_runtime.h>
#include <cuda_fp16.h>
#include <cstdint>

#define BB   4
#define SEQ  8192
#define DIM  256
#define NH   8
#define HD   32
#define MTOT (BB*SEQ)        // 32768
#define QCH  128             // q-stats chunks (64 rows each)
#define CCH  32

// ===================== scratch (device globals) =====================
__device__ __half g_a[7ull * MTOT * 256];        // fp16 activations: q_in, k2..k4, v2..v4
__device__ __half g_c[(size_t)MTOT * 768];       // fp16 concat buffer
__device__ __half g_w[786432];                   // fp16 weights: wq(768x256)|wk,wv(6x256x256)|wf(256x768)
__device__ __half g_k16[3ull * MTOT * DIM];      // fp16 k projections (3 branches)
__device__ __half g_v16[3ull * MTOT * DIM];
__device__ float g_qall[(size_t)MTOT * 768];
__device__ float g_ctx [BB * 24 * HD * HD];
__device__ float g_ctxp[3ull * BB * NH * CCH * HD * HD];   // 12.6 MB
__device__ float g_qm  [BB * 768];
__device__ float g_qs  [BB * 768];               // 1/sum
__device__ float g_qmp [BB * QCH * 768];
__device__ float g_qsp [BB * QCH * 768];

// ===================== helpers =====================
__device__ __forceinline__ uint32_t smem_u32(const void* p){
    uint32_t a;
    asm("{ .reg .u64 t; cvta.to.shared.u64 t, %1; cvt.u32.u64 %0, t; }" : "=r"(a) : "l"(p));
    return a;
}
__device__ __forceinline__ void cp16(uint32_t dst, const void* src){
    asm volatile("cp.async.cg.shared.global [%0], [%1], 16;" :: "r"(dst), "l"(src) : "memory");
}
__device__ __forceinline__ void cp_commit(){ asm volatile("cp.async.commit_group;" ::: "memory"); }
__device__ __forceinline__ void cp_wait1(){ asm volatile("cp.async.wait_group 1;" ::: "memory"); }
__device__ __forceinline__ void cp_wait0(){ asm volatile("cp.async.wait_group 0;" ::: "memory"); }

__device__ __forceinline__ void ldsm4(uint32_t& r0, uint32_t& r1, uint32_t& r2, uint32_t& r3, uint32_t addr){
    asm volatile("ldmatrix.sync.aligned.m8n8.x4.shared.b16 {%0,%1,%2,%3}, [%4];"
        : "=r"(r0), "=r"(r1), "=r"(r2), "=r"(r3) : "r"(addr));
}
__device__ __forceinline__ void mma16816(float* d, const uint32_t* a, const uint32_t* b){
    asm volatile("mma.sync.aligned.m16n8k16.row.col.f32.f16.f16.f32 "
        "{%0,%1,%2,%3}, {%4,%5,%6,%7}, {%8,%9}, {%0,%1,%2,%3};"
        : "+f"(d[0]), "+f"(d[1]), "+f"(d[2]), "+f"(d[3])
        : "r"(a[0]), "r"(a[1]), "r"(a[2]), "r"(a[3]), "r"(b[0]), "r"(b[1]));
}

// ===================== GEMM core (macro-shared mainloop) =====================
#define STG_BYTES 20480
#define GEMM_SMEM (3 * STG_BYTES)

#define GEMM_BODY(A, lda, B, ldb, nkc)                                          \
    const int tid  = threadIdx.x;                                               \
    const int lane = tid & 31, wid = tid >> 5;                                  \
    const int wm = wid >> 2, wn = wid & 3;                                      \
    const int row0 = blockIdx.y * 128;                                          \
    const int col0 = blockIdx.x * 128;                                          \
    float acc[4][4][4];                                                         \
    _Pragma("unroll") for (int i = 0; i < 4; i++)                               \
    _Pragma("unroll") for (int j = 0; j < 4; j++)                               \
    _Pragma("unroll") for (int v = 0; v < 4; v++) acc[i][j][v] = 0.f;           \
    const uint32_t smem_base = smem_u32(smem);                                  \
    const int ch0 = tid * 2;                                                    \
    auto prefetch = [&](int kc) {                                               \
        int s = kc % 3;                                                         \
        uint32_t As = smem_base + s * STG_BYTES;                                \
        uint32_t Bs = As + 10240;                                               \
        _Pragma("unroll") for (int t = 0; t < 2; t++) {                         \
            int ch = ch0 + t;                                                   \
            int r = ch >> 2, c = ch & 3;                                        \
            cp16(As + r * 80 + c * 16, A + (size_t)(row0 + r) * lda + kc * 32 + c * 8); \
            cp16(Bs + r * 80 + c * 16, B + (size_t)(col0 + r) * ldb + kc * 32 + c * 8); \
        }                                                                       \
        cp_commit();                                                            \
    };                                                                          \
    prefetch(0);                                                                \
    if (nkc > 1) prefetch(1);                                                   \
    const int arow = lane & 15, acolh = (lane >> 4) * 8;                        \
    const int bn   = (lane & 7) + (lane >> 4) * 8;                              \
    const int bkh  = ((lane >> 3) & 1) * 8;                                     \
    for (int kc = 0; kc < nkc; kc++) {                                          \
        if (kc + 1 < nkc) cp_wait1(); else cp_wait0();                          \
        __syncthreads();                                                        \
        if (kc + 2 < nkc) prefetch(kc + 2);                                     \
        int s = kc % 3;                                                         \
        uint32_t As = smem_base + s * STG_BYTES;                                \
        uint32_t Bs = As + 10240;                                               \
        _Pragma("unroll") for (int kk = 0; kk < 32; kk += 16) {                 \
            uint32_t af[4][4];                                                  \
            _Pragma("unroll") for (int i = 0; i < 4; i++) {                     \
                uint32_t addr = As + (wm * 64 + i * 16 + arow) * 80 + (kk + acolh) * 2; \
                ldsm4(af[i][0], af[i][1], af[i][2], af[i][3], addr);            \
            }                                                                   \
            uint32_t bf[4][2];                                                  \
            _Pragma("unroll") for (int jp = 0; jp < 2; jp++) {                  \
                uint32_t addr = Bs + (wn * 32 + jp * 16 + bn) * 80 + (kk + bkh) * 2; \
                ldsm4(bf[2*jp][0], bf[2*jp][1], bf[2*jp+1][0], bf[2*jp+1][1], addr); \
            }                                                                   \
            _Pragma("unroll") for (int i = 0; i < 4; i++)                       \
            _Pragma("unroll") for (int j = 0; j < 4; j++)                       \
                mma16816(acc[i][j], af[i], bf[j]);                              \
        }                                                                       \
    }

// fp32-output GEMM (qall / final)
__global__ void __launch_bounds__(256, 2)
gemm_mma(const __half* __restrict__ Ag, int lda,
         const __half* __restrict__ Bg, int ldb,
         const float* __restrict__ bias, float* __restrict__ C, int N, int KH)
{
    extern __shared__ __align__(16) char smem[];
    GEMM_BODY(Ag, lda, Bg, ldb, KH)

    const int g = lane >> 2, tg = lane & 3;
    float2 bb[4];
#pragma unroll
    for (int j = 0; j < 4; j++) {
        int c = col0 + wn * 32 + j * 8 + 2 * tg;
        bb[j] = make_float2(bias[c], bias[c + 1]);
    }
#pragma unroll
    for (int i = 0; i < 4; i++) {
        int r = row0 + wm * 64 + i * 16 + g;
#pragma unroll
        for (int j = 0; j < 4; j++) {
            int c = col0 + wn * 32 + j * 8 + 2 * tg;
            *reinterpret_cast<float2*>(C + (size_t)r * N + c) =
                make_float2(acc[i][j][0] + bb[j].x, acc[i][j][1] + bb[j].y);
            *reinterpret_cast<float2*>(C + (size_t)(r + 8) * N + c) =
                make_float2(acc[i][j][2] + bb[j].x, acc[i][j][3] + bb[j].y);
        }
    }
}

// batched k/v GEMM: z = 0..5 -> branch = z%3, kv = z/3; fp16 output
__global__ void __launch_bounds__(256, 2)
gemm_kv(const __half* __restrict__ abuf, const __half* __restrict__ wkv,
        const float* __restrict__ bk, const float* __restrict__ bv)
{
    extern __shared__ __align__(16) char smem[];
    const int z = blockIdx.z;
    const int branch = z % 3, kv = z / 3;
    const __half* Ag = abuf + (size_t)(1 + branch + 3 * kv) * MTOT * 256;
    const __half* Bg = wkv + (size_t)(3 * kv + branch) * 65536;
    const float* bias = (kv ? bv : bk) + branch * 256;
    __half* C = (kv ? g_v16 : g_k16) + (size_t)branch * MTOT * 256;

    GEMM_BODY(Ag, 256, Bg, 256, 8)

    const int g = lane >> 2, tg = lane & 3;
    float2 bb[4];
#pragma unroll
    for (int j = 0; j < 4; j++) {
        int c = col0 + wn * 32 + j * 8 + 2 * tg;
        bb[j] = make_float2(bias[c], bias[c + 1]);
    }
#pragma unroll
    for (int i = 0; i < 4; i++) {
        int r = row0 + wm * 64 + i * 16 + g;
#pragma unroll
        for (int j = 0; j < 4; j++) {
            int c = col0 + wn * 32 + j * 8 + 2 * tg;
            *reinterpret_cast<__half2*>(C + (size_t)r * 256 + c) =
                __floats2half2_rn(acc[i][j][0] + bb[j].x, acc[i][j][1] + bb[j].y);
            *reinterpret_cast<__half2*>(C + (size_t)(r + 8) * 256 + c) =
                __floats2half2_rn(acc[i][j][2] + bb[j].x, acc[i][j][3] + bb[j].y);
        }
    }
}

// ===================== prep kernels =====================
__device__ __forceinline__ uint2 cvt4(float4 x)
{
    union { __half2 h2[2]; uint2 u; } U;
    U.h2[0] = __floats2half2_rn(x.x, x.y);
    U.h2[1] = __floats2half2_rn(x.z, x.w);
    return U.u;
}

__global__ void __launch_bounds__(256)
prep_q(const float* __restrict__ a, const float* __restrict__ b,
       __half* __restrict__ o, int n4)
{
    int i = blockIdx.x * 256 + threadIdx.x;
    if (i >= n4) return;
    float4 x = reinterpret_cast<const float4*>(a)[i];
    float4 y = reinterpret_cast<const float4*>(b)[i];
    x.x += y.x; x.y += y.y; x.z += y.z; x.w += y.w;
    reinterpret_cast<uint2*>(o)[i] = cvt4(x);
}

__global__ void __launch_bounds__(256)
prep_kv(const float* __restrict__ f, const float* __restrict__ pe,
        __half* __restrict__ ok, __half* __restrict__ ov, int n4)
{
    int i = blockIdx.x * 256 + threadIdx.x;
    if (i >= n4) return;
    float4 x = reinterpret_cast<const float4*>(f)[i];
    float4 y = reinterpret_cast<const float4*>(pe)[i];
    float4 k = make_float4(x.x + y.x, x.y + y.y, x.z + y.z, x.w + y.w);
    reinterpret_cast<uint2*>(ok)[i] = cvt4(k);
    reinterpret_cast<uint2*>(ov)[i] = cvt4(x);
}

__global__ void __launch_bounds__(256)
prep_w_all(const float* __restrict__ Wq, const float* __restrict__ Wk,
           const float* __restrict__ Wv, const float* __restrict__ Wrp,
           __half* __restrict__ o)
{
    int t = blockIdx.x * 256 + threadIdx.x;
    if (t < 589824) {
        int mat = t >> 16, idx = t & 65535;
        int n = idx >> 8, k = idx & 255;
        const float* W = (mat < 3) ? Wq + (size_t)mat * 65536
                       : (mat < 6) ? Wk + (size_t)(mat - 3) * 65536
                                   : Wv + (size_t)(mat - 6) * 65536;
        o[(size_t)mat * 65536 + (size_t)n * 256 + k] = __float2half_rn(W[k * 256 + n]);
    } else {
        int idx = t - 589824;
        int n = idx / 768, k = idx - n * 768;
        o[589824 + (size_t)n * 768 + k] = __float2half_rn(Wrp[(size_t)k * 256 + n]);
    }
}

// ===================== q softmax stats over sequence axis (768 ch) ==========
__global__ void qstats_part_kernel()
{
    int b = blockIdx.x, ch = blockIdx.y, c = blockIdx.z * 256 + threadIdx.x;
    const int ROWS = SEQ / QCH;                       // 64
    const float* p = g_qall + ((size_t)b * SEQ + (size_t)ch * ROWS) * 768 + c;
    float m0=-1e30f,m1=-1e30f,m2=-1e30f,m3=-1e30f, s0=0.f,s1=0.f,s2=0.f,s3=0.f;
    for (int r = 0; r < ROWS; r += 4) {
        float x0 = p[(size_t)(r+0)*768], x1 = p[(size_t)(r+1)*768];
        float x2 = p[(size_t)(r+2)*768], x3 = p[(size_t)(r+3)*768];
        float nm;
        nm = fmaxf(m0,x0); s0 = s0*__expf(m0-nm)+__expf(x0-nm); m0 = nm;
        nm = fmaxf(m1,x1); s1 = s1*__expf(m1-nm)+__expf(x1-nm); m1 = nm;
        nm = fmaxf(m2,x2); s2 = s2*__expf(m2-nm)+__expf(x2-nm); m2 = nm;
        nm = fmaxf(m3,x3); s3 = s3*__expf(m3-nm)+__expf(x3-nm); m3 = nm;
    }
    float m = fmaxf(fmaxf(m0,m1), fmaxf(m2,m3));
    float s = s0*__expf(m0-m) + s1*__expf(m1-m) + s2*__expf(m2-m) + s3*__expf(m3-m);
    g_qmp[((size_t)b*QCH+ch)*768 + c] = m;
    g_qsp[((size_t)b*QCH+ch)*768 + c] = s;
}

__global__ void qstats_reduce_kernel()
{
    int b = blockIdx.x, c = blockIdx.y * 256 + threadIdx.x;
    float m = -1e30f;
    for (int ch = 0; ch < QCH; ch++) m = fmaxf(m, g_qmp[((size_t)b*QCH+ch)*768 + c]);
    float s = 0.f;
    for (int ch = 0; ch < QCH; ch++)
        s += g_qsp[((size_t)b*QCH+ch)*768 + c] * __expf(g_qmp[((size_t)b*QCH+ch)*768 + c] - m);
    g_qm[b*768 + c] = m;
    g_qs[b*768 + c] = 1.f / s;
}

// ===================== ctx = softmax_c(k)^T v — register-blocked, fp16 in ====
// grid (1024, 3): x -> (b, h, chunk), y = branch. 256 threads.
__global__ void __launch_bounds__(256)
ctx_part_kernel()
{
    __shared__ float ks[32][40];
    __shared__ float vs[32][40];
    __shared__ float red[3][64][16];

    int x = blockIdx.x, branch = blockIdx.y;
    int chunk = x & 31, h = (x >> 5) & 7, b = x >> 8;
    int tid = threadIdx.x;
    int row = tid >> 3, c4 = (tid & 7) * 4;        // load/softmax coords
    int g = tid >> 6, slot = tid & 63;             // compute coords
    int c0 = (slot >> 3) * 4, d0 = (slot & 7) * 4;

    float acc[4][4];
#pragma unroll
    for (int i = 0; i < 4; i++)
#pragma unroll
        for (int j = 0; j < 4; j++) acc[i][j] = 0.f;

    const size_t base = ((size_t)branch * MTOT + (size_t)b * SEQ + (size_t)chunk * 256) * DIM + h * HD;

    for (int t = 0; t < 8; t++) {
        const __half* kp = g_k16 + base + (size_t)(t * 32 + row) * DIM + c4;
        const __half* vp = g_v16 + base + (size_t)(t * 32 + row) * DIM + c4;
        uint2 ku = *reinterpret_cast<const uint2*>(kp);
        uint2 vu = *reinterpret_cast<const uint2*>(vp);
        float2 k01 = __half22float2(*reinterpret_cast<__half2*>(&ku.x));
        float2 k23 = __half22float2(*reinterpret_cast<__half2*>(&ku.y));
        float2 v01 = __half22float2(*reinterpret_cast<__half2*>(&vu.x));
        float2 v23 = __half22float2(*reinterpret_cast<__half2*>(&vu.y));

        // row max over this thread's 4 + 8-lane group
        float m = fmaxf(fmaxf(k01.x, k01.y), fmaxf(k23.x, k23.y));
#pragma unroll
        for (int o = 1; o < 8; o <<= 1) m = fmaxf(m, __shfl_xor_sync(0xffffffffu, m, o));
        float e0 = __expf(k01.x - m), e1 = __expf(k01.y - m);
        float e2 = __expf(k23.x - m), e3 = __expf(k23.y - m);
        float s = e0 + e1 + e2 + e3;
#pragma unroll
        for (int o = 1; o < 8; o <<= 1) s += __shfl_xor_sync(0xffffffffu, s, o);
        float inv = 1.f / s;

        __syncthreads();                            // previous tile fully consumed
        *reinterpret_cast<float4*>(&ks[row][c4]) = make_float4(e0*inv, e1*inv, e2*inv, e3*inv);
        *reinterpret_cast<float4*>(&vs[row][c4]) = make_float4(v01.x, v01.y, v23.x, v23.y);
        __syncthreads();

#pragma unroll
        for (int r8 = 0; r8 < 8; r8++) {
            int rr = g * 8 + r8;
            float4 kc = *reinterpret_cast<float4*>(&ks[rr][c0]);
            float4 vd = *reinterpret_cast<float4*>(&vs[rr][d0]);
            acc[0][0] += kc.x * vd.x; acc[0][1] += kc.x * vd.y;
            acc[0][2] += kc.x * vd.z; acc[0][3] += kc.x * vd.w;
            acc[1][0] += kc.y * vd.x; acc[1][1] += kc.y * vd.y;
            acc[1][2] += kc.y * vd.z; acc[1][3] += kc.y * vd.w;
            acc[2][0] += kc.z * vd.x; acc[2][1] += kc.z * vd.y;
            acc[2][2] += kc.z * vd.z; acc[2][3] += kc.z * vd.w;
            acc[3][0] += kc.w * vd.x; acc[3][1] += kc.w * vd.y;
            acc[3][2] += kc.w * vd.z; acc[3][3] += kc.w * vd.w;
        }
    }

    // cross-group reduction
    if (g > 0) {
#pragma unroll
        for (int i = 0; i < 4; i++)
            *reinterpret_cast<float4*>(&red[g-1][slot][i*4]) =
                make_float4(acc[i][0], acc[i][1], acc[i][2], acc[i][3]);
    }
    __syncthreads();
    if (g == 0) {
#pragma unroll
        for (int gg = 0; gg < 3; gg++)
#pragma unroll
            for (int i = 0; i < 4; i++) {
                float4 r4 = *reinterpret_cast<float4*>(&red[gg][slot][i*4]);
                acc[i][0] += r4.x; acc[i][1] += r4.y; acc[i][2] += r4.z; acc[i][3] += r4.w;
            }
        float* op = g_ctxp + ((size_t)branch * 1024 + x) * 1024;
#pragma unroll
        for (int i = 0; i < 4; i++)
            *reinterpret_cast<float4*>(op + (c0 + i) * 32 + d0) =
                make_float4(acc[i][0], acc[i][1], acc[i][2], acc[i][3]);
    }
}

// grid (BB*NH, 3), 1024 threads
__global__ void __launch_bounds__(1024)
ctx_reduce_kernel()
{
    int bh = blockIdx.x, branch = blockIdx.y, tid = threadIdx.x;
    int b = bh >> 3, h = bh & 7;
    size_t base_x = (size_t)b * 256 + h * 32;
    float s = 0.f;
    for (int ch = 0; ch < CCH; ch++)
        s += g_ctxp[((size_t)branch * 1024 + base_x + ch) * 1024 + tid];
    g_ctx[((size_t)b * 24 + branch * 8 + h) * 1024 + tid] = s;
}

// ===================== attend: all 3 branches, ctx in registers ==============
__global__ void __launch_bounds__(384, 1)
att_kernel()
{
    __shared__ float sq_s[8][768];
    __shared__ float qm_s[768];
    __shared__ float qi_s[768];

    int blk = blockIdx.x;
    int b   = blk / (SEQ/32);
    int n0  = (blk % (SEQ/32)) * 32;
    int tid = threadIdx.x;
    int ch0 = tid * 2;
    int h24 = ch0 >> 5;
    int d0  = ch0 & 31;

    float cr[32][2];
    const float* cp = g_ctx + ((size_t)b*24 + h24) * (HD*HD) + d0;
    #pragma unroll
    for (int c = 0; c < 32; c++) {
        float2 v = *reinterpret_cast<const float2*>(cp + c*32);
        cr[c][0] = v.x; cr[c][1] = v.y;
    }
    {
        float2 m2 = *reinterpret_cast<const float2*>(g_qm + b*768 + ch0);
        float2 i2 = *reinterpret_cast<const float2*>(g_qs + b*768 + ch0);
        qm_s[ch0] = m2.x; qm_s[ch0+1] = m2.y;
        qi_s[ch0] = i2.x; qi_s[ch0+1] = i2.y;
    }
    __syncthreads();

    const float* qrow = g_qall + ((size_t)b*SEQ + n0) * 768;
    __half* orow = g_c + ((size_t)b*SEQ + n0) * 768;

    for (int chunk = 0; chunk < 4; chunk++) {
        #pragma unroll
        for (int v = 0; v < 4; v++) {
            int idx = v * 384 + tid;
            int r = idx / 192, col = (idx - r * 192) * 4;
            float4 x = *reinterpret_cast<const float4*>(qrow + (size_t)(chunk*8 + r)*768 + col);
            float4 m = *reinterpret_cast<const float4*>(qm_s + col);
            float4 iv = *reinterpret_cast<const float4*>(qi_s + col);
            float4 sq = make_float4(__expf(x.x - m.x) * iv.x, __expf(x.y - m.y) * iv.y,
                                    __expf(x.z - m.z) * iv.z, __expf(x.w - m.w) * iv.w);
            *reinterpret_cast<float4*>(&sq_s[r][col]) = sq;
        }
        __syncthreads();

        #pragma unroll
        for (int n = 0; n < 8; n++) {
            float4 s4[8];
            const float4* sp = reinterpret_cast<const float4*>(&sq_s[n][h24 * 32]);
            #pragma unroll
            for (int u = 0; u < 8; u++) s4[u] = sp[u];
            const float* s = reinterpret_cast<const float*>(s4);
            float a0 = 0.f, a1 = 0.f;
            #pragma unroll
            for (int c = 0; c < 32; c++) { a0 += cr[c][0] * s[c]; a1 += cr[c][1] * s[c]; }

            *reinterpret_cast<__half2*>(orow + (size_t)(chunk*8 + n) * 768 + ch0) =
                __floats2half2_rn(a0, a1);
        }
        __syncthreads();
    }
}

// ===================== launcher =====================
extern "C" void kernel_launch(void* const* d_in, const int* in_sizes, int n_in,
                              void* d_out, int out_size)
{
    const float* f[4]   = {(const float*)d_in[0], (const float*)d_in[1],
                           (const float*)d_in[2], (const float*)d_in[3]};
    const float* fpe[4] = {(const float*)d_in[4], (const float*)d_in[5],
                           (const float*)d_in[6], (const float*)d_in[7]};
    const float* Wq  = (const float*)d_in[8];
    const float* bq  = (const float*)d_in[9];
    const float* Wk  = (const float*)d_in[10];
    const float* bk  = (const float*)d_in[11];
    const float* Wv  = (const float*)d_in[12];
    const float* bv  = (const float*)d_in[13];
    const float* Wrp = (const float*)d_in[14];
    const float* brp = (const float*)d_in[15];
    float* out = (float*)d_out;

    cudaFuncSetAttribute(gemm_mma, cudaFuncAttributeMaxDynamicSharedMemorySize, GEMM_SMEM);
    cudaFuncSetAttribute(gemm_kv,  cudaFuncAttributeMaxDynamicSharedMemorySize, GEMM_SMEM);

    float* qall;
    __half *abuf, *cbuf, *wbuf;
    cudaGetSymbolAddress((void**)&qall, g_qall);
    cudaGetSymbolAddress((void**)&abuf, g_a);
    cudaGetSymbolAddress((void**)&cbuf, g_c);
    cudaGetSymbolAddress((void**)&wbuf, g_w);

    const size_t AS = (size_t)MTOT * 256;
    const int n4 = MTOT * DIM / 4;
    const int pb = n4 / 256;

    __half* wq = wbuf;                    // [768][256]
    __half* wk = wbuf + 196608;           // 3 x [256][256], then wv 3 x
    __half* wf = wbuf + 589824;           // [256][768]

    // launches 1-5
    prep_q<<<pb, 256>>>(f[0], fpe[0], abuf, n4);
    prep_w_all<<<3072, 256>>>(Wq, Wk, Wv, Wrp, wbuf);
    for (int i = 1; i <= 3; i++)
        prep_kv<<<pb, 256>>>(f[i], fpe[i], abuf + i * AS, abuf + (3 + i) * AS, n4);

    // launch 6 (ncu slot): qall = q_in @ [Wq0|Wq1|Wq2]
    gemm_mma<<<dim3(6, MTOT/128, 1), 256, GEMM_SMEM>>>(abuf, 256, wq, 256, bq, qall, 768, 8);

    // all 6 k/v GEMMs in one launch, fp16 out
    gemm_kv<<<dim3(2, MTOT/128, 6), 256, GEMM_SMEM>>>(abuf, wk, bk, bv);

    // ctx for all branches
    ctx_part_kernel  <<<dim3(BB * NH * CCH, 3), 256>>>();
    ctx_reduce_kernel<<<dim3(BB * NH, 3), 1024>>>();

    qstats_part_kernel  <<<dim3(BB, QCH, 3), 256>>>();
    qstats_reduce_kernel<<<dim3(BB, 3), 256>>>();

    att_kernel<<<BB * (SEQ / 32), 384>>>();

    // out = cat @ Wrp + brp
    gemm_mma<<<dim3(2, MTOT/128, 1), 256, GEMM_SMEM>>>(cbuf, 768, wf, 768, brp, out, 256, 24);
}

// round 8
// speedup vs baseline: 4.8223x; 1.0863x over previous
#include <cuda_runtime.h>
#include <cuda_fp16.h>
#include <cstdint>

#define BB   4
#define SEQ  8192
#define DIM  256
#define NH   8
#define HD   32
#define MTOT (BB*SEQ)        // 32768
#define QCH  128             // q-sum chunks (64 rows each)
#define CCH  32

// ===================== scratch (device globals) =====================
__device__ __half g_a[7ull * MTOT * 256];        // fp16 activations: q_in, k2..k4, v2..v4
__device__ __half g_q16[(size_t)MTOT * 768];     // fp16 qall projections
__device__ __half g_sq[(size_t)MTOT * 768];      // fp16 softq (scaled by 1024)
__device__ __half g_w[786432];                   // fp16 weights: wq|wk,wv|wf(256x768)
__device__ __half g_E[4ull * 256 * 768];         // per-batch effective final weights
__device__ __half g_k16[3ull * MTOT * DIM];
__device__ __half g_v16[3ull * MTOT * DIM];
__device__ float g_ctx [BB * 24 * HD * HD];
__device__ float g_ctxp[3ull * BB * NH * CCH * HD * HD];
__device__ float g_qs  [BB * 768];               // 1024 / sumexp
__device__ float g_qsp [BB * QCH * 768];

// ===================== helpers =====================
__device__ __forceinline__ uint32_t smem_u32(const void* p){
    uint32_t a;
    asm("{ .reg .u64 t; cvta.to.shared.u64 t, %1; cvt.u32.u64 %0, t; }" : "=r"(a) : "l"(p));
    return a;
}
__device__ __forceinline__ void cp16(uint32_t dst, const void* src){
    asm volatile("cp.async.cg.shared.global [%0], [%1], 16;" :: "r"(dst), "l"(src) : "memory");
}
__device__ __forceinline__ void cp_commit(){ asm volatile("cp.async.commit_group;" ::: "memory"); }
__device__ __forceinline__ void cp_wait1(){ asm volatile("cp.async.wait_group 1;" ::: "memory"); }
__device__ __forceinline__ void cp_wait0(){ asm volatile("cp.async.wait_group 0;" ::: "memory"); }

__device__ __forceinline__ void ldsm4(uint32_t& r0, uint32_t& r1, uint32_t& r2, uint32_t& r3, uint32_t addr){
    asm volatile("ldmatrix.sync.aligned.m8n8.x4.shared.b16 {%0,%1,%2,%3}, [%4];"
        : "=r"(r0), "=r"(r1), "=r"(r2), "=r"(r3) : "r"(addr));
}
__device__ __forceinline__ void mma16816(float* d, const uint32_t* a, const uint32_t* b){
    asm volatile("mma.sync.aligned.m16n8k16.row.col.f32.f16.f16.f32 "
        "{%0,%1,%2,%3}, {%4,%5,%6,%7}, {%8,%9}, {%0,%1,%2,%3};"
        : "+f"(d[0]), "+f"(d[1]), "+f"(d[2]), "+f"(d[3])
        : "r"(a[0]), "r"(a[1]), "r"(a[2]), "r"(a[3]), "r"(b[0]), "r"(b[1]));
}

// ===================== GEMM core (macro-shared mainloop) =====================
#define STG_BYTES 20480
#define GEMM_SMEM (3 * STG_BYTES)

#define GEMM_BODY(A, lda, B, ldb, nkc)                                          \
    const int tid  = threadIdx.x;                                               \
    const int lane = tid & 31, wid = tid >> 5;                                  \
    const int wm = wid >> 2, wn = wid & 3;                                      \
    const int row0 = blockIdx.y * 128;                                          \
    const int col0 = blockIdx.x * 128;                                          \
    float acc[4][4][4];                                                         \
    _Pragma("unroll") for (int i = 0; i < 4; i++)                               \
    _Pragma("unroll") for (int j = 0; j < 4; j++)                               \
    _Pragma("unroll") for (int v = 0; v < 4; v++) acc[i][j][v] = 0.f;           \
    const uint32_t smem_base = smem_u32(smem);                                  \
    const int ch0 = tid * 2;                                                    \
    auto prefetch = [&](int kc) {                                               \
        int s = kc % 3;                                                         \
        uint32_t As = smem_base + s * STG_BYTES;                                \
        uint32_t Bs = As + 10240;                                               \
        _Pragma("unroll") for (int t = 0; t < 2; t++) {                         \
            int ch = ch0 + t;                                                   \
            int r = ch >> 2, c = ch & 3;                                        \
            cp16(As + r * 80 + c * 16, A + (size_t)(row0 + r) * lda + kc * 32 + c * 8); \
            cp16(Bs + r * 80 + c * 16, B + (size_t)(col0 + r) * ldb + kc * 32 + c * 8); \
        }                                                                       \
        cp_commit();                                                            \
    };                                                                          \
    prefetch(0);                                                                \
    if (nkc > 1) prefetch(1);                                                   \
    const int arow = lane & 15, acolh = (lane >> 4) * 8;                        \
    const int bn   = (lane & 7) + (lane >> 4) * 8;                              \
    const int bkh  = ((lane >> 3) & 1) * 8;                                     \
    for (int kc = 0; kc < nkc; kc++) {                                          \
        if (kc + 1 < nkc) cp_wait1(); else cp_wait0();                          \
        __syncthreads();                                                        \
        if (kc + 2 < nkc) prefetch(kc + 2);                                     \
        int s = kc % 3;                                                         \
        uint32_t As = smem_base + s * STG_BYTES;                                \
        uint32_t Bs = As + 10240;                                               \
        _Pragma("unroll") for (int kk = 0; kk < 32; kk += 16) {                 \
            uint32_t af[4][4];                                                  \
            _Pragma("unroll") for (int i = 0; i < 4; i++) {                     \
                uint32_t addr = As + (wm * 64 + i * 16 + arow) * 80 + (kk + acolh) * 2; \
                ldsm4(af[i][0], af[i][1], af[i][2], af[i][3], addr);            \
            }                                                                   \
            uint32_t bf[4][2];                                                  \
            _Pragma("unroll") for (int jp = 0; jp < 2; jp++) {                  \
                uint32_t addr = Bs + (wn * 32 + jp * 16 + bn) * 80 + (kk + bkh) * 2; \
                ldsm4(bf[2*jp][0], bf[2*jp][1], bf[2*jp+1][0], bf[2*jp+1][1], addr); \
            }                                                                   \
            _Pragma("unroll") for (int i = 0; i < 4; i++)                       \
            _Pragma("unroll") for (int j = 0; j < 4; j++)                       \
                mma16816(acc[i][j], af[i], bf[j]);                              \
        }                                                                       \
    }

// fp16-output GEMM (qall)
__global__ void __launch_bounds__(256, 2)
gemm_f16out(const __half* __restrict__ Ag, int lda,
            const __half* __restrict__ Bg, int ldb,
            const float* __restrict__ bias, __half* __restrict__ C, int N, int KH)
{
    extern __shared__ __align__(16) char smem[];
    GEMM_BODY(Ag, lda, Bg, ldb, KH)

    const int g = lane >> 2, tg = lane & 3;
    float2 bb[4];
#pragma unroll
    for (int j = 0; j < 4; j++) {
        int c = col0 + wn * 32 + j * 8 + 2 * tg;
        bb[j] = make_float2(bias[c], bias[c + 1]);
    }
#pragma unroll
    for (int i = 0; i < 4; i++) {
        int r = row0 + wm * 64 + i * 16 + g;
#pragma unroll
        for (int j = 0; j < 4; j++) {
            int c = col0 + wn * 32 + j * 8 + 2 * tg;
            *reinterpret_cast<__half2*>(C + (size_t)r * N + c) =
                __floats2half2_rn(acc[i][j][0] + bb[j].x, acc[i][j][1] + bb[j].y);
            *reinterpret_cast<__half2*>(C + (size_t)(r + 8) * N + c) =
                __floats2half2_rn(acc[i][j][2] + bb[j].x, acc[i][j][3] + bb[j].y);
        }
    }
}

// fp32-output GEMM with per-batch B (final): B += (blockIdx.y>>6)*bstride
__global__ void __launch_bounds__(256, 2)
gemm_f32out(const __half* __restrict__ Ag, int lda,
            const __half* __restrict__ Bg0, int ldb, size_t bstride,
            const float* __restrict__ bias, float* __restrict__ C, int N, int KH)
{
    extern __shared__ __align__(16) char smem[];
    const __half* Bg = Bg0 + (size_t)(blockIdx.y >> 6) * bstride;
    GEMM_BODY(Ag, lda, Bg, ldb, KH)

    const int g = lane >> 2, tg = lane & 3;
    float2 bb[4];
#pragma unroll
    for (int j = 0; j < 4; j++) {
        int c = col0 + wn * 32 + j * 8 + 2 * tg;
        bb[j] = make_float2(bias[c], bias[c + 1]);
    }
#pragma unroll
    for (int i = 0; i < 4; i++) {
        int r = row0 + wm * 64 + i * 16 + g;
#pragma unroll
        for (int j = 0; j < 4; j++) {
            int c = col0 + wn * 32 + j * 8 + 2 * tg;
            *reinterpret_cast<float2*>(C + (size_t)r * N + c) =
                make_float2(acc[i][j][0] + bb[j].x, acc[i][j][1] + bb[j].y);
            *reinterpret_cast<float2*>(C + (size_t)(r + 8) * N + c) =
                make_float2(acc[i][j][2] + bb[j].x, acc[i][j][3] + bb[j].y);
        }
    }
}

// batched k/v GEMM: z = 0..5 -> branch = z%3, kv = z/3; fp16 output
__global__ void __launch_bounds__(256, 2)
gemm_kv(const __half* __restrict__ abuf, const __half* __restrict__ wkv,
        const float* __restrict__ bk, const float* __restrict__ bv)
{
    extern __shared__ __align__(16) char smem[];
    const int z = blockIdx.z;
    const int branch = z % 3, kv = z / 3;
    const __half* Ag = abuf + (size_t)(1 + branch + 3 * kv) * MTOT * 256;
    const __half* Bg = wkv + (size_t)(3 * kv + branch) * 65536;
    const float* bias = (kv ? bv : bk) + branch * 256;
    __half* C = (kv ? g_v16 : g_k16) + (size_t)branch * MTOT * 256;

    GEMM_BODY(Ag, 256, Bg, 256, 8)

    const int g = lane >> 2, tg = lane & 3;
    float2 bb[4];
#pragma unroll
    for (int j = 0; j < 4; j++) {
        int c = col0 + wn * 32 + j * 8 + 2 * tg;
        bb[j] = make_float2(bias[c], bias[c + 1]);
    }
#pragma unroll
    for (int i = 0; i < 4; i++) {
        int r = row0 + wm * 64 + i * 16 + g;
#pragma unroll
        for (int j = 0; j < 4; j++) {
            int c = col0 + wn * 32 + j * 8 + 2 * tg;
            *reinterpret_cast<__half2*>(C + (size_t)r * 256 + c) =
                __floats2half2_rn(acc[i][j][0] + bb[j].x, acc[i][j][1] + bb[j].y);
            *reinterpret_cast<__half2*>(C + (size_t)(r + 8) * 256 + c) =
                __floats2half2_rn(acc[i][j][2] + bb[j].x, acc[i][j][3] + bb[j].y);
        }
    }
}

// ===================== prep kernels =====================
__device__ __forceinline__ uint2 cvt4(float4 x)
{
    union { __half2 h2[2]; uint2 u; } U;
    U.h2[0] = __floats2half2_rn(x.x, x.y);
    U.h2[1] = __floats2half2_rn(x.z, x.w);
    return U.u;
}

__global__ void __launch_bounds__(256)
prep_q(const float* __restrict__ a, const float* __restrict__ b,
       __half* __restrict__ o, int n4)
{
    int i = blockIdx.x * 256 + threadIdx.x;
    if (i >= n4) return;
    float4 x = reinterpret_cast<const float4*>(a)[i];
    float4 y = reinterpret_cast<const float4*>(b)[i];
    x.x += y.x; x.y += y.y; x.z += y.z; x.w += y.w;
    reinterpret_cast<uint2*>(o)[i] = cvt4(x);
}

__global__ void __launch_bounds__(256)
prep_kv(const float* __restrict__ f, const float* __restrict__ pe,
        __half* __restrict__ ok, __half* __restrict__ ov, int n4)
{
    int i = blockIdx.x * 256 + threadIdx.x;
    if (i >= n4) return;
    float4 x = reinterpret_cast<const float4*>(f)[i];
    float4 y = reinterpret_cast<const float4*>(pe)[i];
    float4 k = make_float4(x.x + y.x, x.y + y.y, x.z + y.z, x.w + y.w);
    reinterpret_cast<uint2*>(ok)[i] = cvt4(k);
    reinterpret_cast<uint2*>(ov)[i] = cvt4(x);
}

__global__ void __launch_bounds__(256)
prep_w_all(const float* __restrict__ Wq, const float* __restrict__ Wk,
           const float* __restrict__ Wv, const float* __restrict__ Wrp,
           __half* __restrict__ o)
{
    int t = blockIdx.x * 256 + threadIdx.x;
    if (t < 589824) {
        int mat = t >> 16, idx = t & 65535;
        int n = idx >> 8, k = idx & 255;
        const float* W = (mat < 3) ? Wq + (size_t)mat * 65536
                       : (mat < 6) ? Wk + (size_t)(mat - 3) * 65536
                                   : Wv + (size_t)(mat - 6) * 65536;
        o[(size_t)mat * 65536 + (size_t)n * 256 + k] = __float2half_rn(W[k * 256 + n]);
    } else {
        int idx = t - 589824;
        int n = idx / 768, k = idx - n * 768;
        o[589824 + (size_t)n * 768 + k] = __float2half_rn(Wrp[(size_t)k * 256 + n]);
    }
}

// ===================== q sumexp over sequence axis (no max needed) ==========
__global__ void qsum_part_kernel()
{
    int b = blockIdx.x, ch = blockIdx.y, c = blockIdx.z * 256 + threadIdx.x;
    const int ROWS = SEQ / QCH;                       // 64
    const __half* p = g_q16 + ((size_t)b * SEQ + (size_t)ch * ROWS) * 768 + c;
    float s0 = 0.f, s1 = 0.f, s2 = 0.f, s3 = 0.f;
    for (int r = 0; r < ROWS; r += 4) {
        s0 += __expf(__half2float(p[(size_t)(r+0)*768]));
        s1 += __expf(__half2float(p[(size_t)(r+1)*768]));
        s2 += __expf(__half2float(p[(size_t)(r+2)*768]));
        s3 += __expf(__half2float(p[(size_t)(r+3)*768]));
    }
    g_qsp[((size_t)b*QCH+ch)*768 + c] = (s0 + s1) + (s2 + s3);
}

__global__ void qsum_reduce_kernel()
{
    int b = blockIdx.x, c = blockIdx.y * 256 + threadIdx.x;
    float s = 0.f;
    for (int ch = 0; ch < QCH; ch++)
        s += g_qsp[((size_t)b*QCH+ch)*768 + c];
    g_qs[b*768 + c] = 1024.f / s;                     // scale folded in; E carries 1/1024
}

// softq = exp(q) * (1024/sum)  -> fp16 ; 8 halves per thread
__global__ void __launch_bounds__(256)
softq_kernel()
{
    int i = blockIdx.x * 256 + threadIdx.x;           // over MTOT*768/8
    int row = i / 96;
    int cu  = (i - row * 96) * 8;
    int b   = row >> 13;
    const float* inv = g_qs + b * 768 + cu;
    uint4 qv = reinterpret_cast<const uint4*>(g_q16)[i];
    const __half2* h = reinterpret_cast<const __half2*>(&qv);
    uint4 ov;
    __half2* oh = reinterpret_cast<__half2*>(&ov);
#pragma unroll
    for (int u = 0; u < 4; u++) {
        float2 x = __half22float2(h[u]);
        oh[u] = __floats2half2_rn(__expf(x.x) * inv[2*u], __expf(x.y) * inv[2*u+1]);
    }
    reinterpret_cast<uint4*>(g_sq)[i] = ov;
}

// ===================== ctx = softmax_c(k)^T v — register-blocked =============
// grid (1024, 3): x -> (b, h, chunk), y = branch. 256 threads.
__global__ void __launch_bounds__(256)
ctx_part_kernel()
{
    __shared__ float ks[32][40];
    __shared__ float vs[32][40];
    __shared__ float red[3][64][16];

    int x = blockIdx.x, branch = blockIdx.y;
    int chunk = x & 31, h = (x >> 5) & 7, b = x >> 8;
    int tid = threadIdx.x;
    int row = tid >> 3, c4 = (tid & 7) * 4;
    int g = tid >> 6, slot = tid & 63;
    int c0 = (slot >> 3) * 4, d0 = (slot & 7) * 4;

    float acc[4][4];
#pragma unroll
    for (int i = 0; i < 4; i++)
#pragma unroll
        for (int j = 0; j < 4; j++) acc[i][j] = 0.f;

    const size_t base = ((size_t)branch * MTOT + (size_t)b * SEQ + (size_t)chunk * 256) * DIM + h * HD;

    for (int t = 0; t < 8; t++) {
        const __half* kp = g_k16 + base + (size_t)(t * 32 + row) * DIM + c4;
        const __half* vp = g_v16 + base + (size_t)(t * 32 + row) * DIM + c4;
        uint2 ku = *reinterpret_cast<const uint2*>(kp);
        uint2 vu = *reinterpret_cast<const uint2*>(vp);
        float2 k01 = __half22float2(*reinterpret_cast<__half2*>(&ku.x));
        float2 k23 = __half22float2(*reinterpret_cast<__half2*>(&ku.y));
        float2 v01 = __half22float2(*reinterpret_cast<__half2*>(&vu.x));
        float2 v23 = __half22float2(*reinterpret_cast<__half2*>(&vu.y));

        // k-softmax over 32 channels, no max subtraction (|k| small)
        float e0 = __expf(k01.x), e1 = __expf(k01.y);
        float e2 = __expf(k23.x), e3 = __expf(k23.y);
        float s = (e0 + e1) + (e2 + e3);
#pragma unroll
        for (int o = 1; o < 8; o <<= 1) s += __shfl_xor_sync(0xffffffffu, s, o);
        float inv = 1.f / s;

        __syncthreads();
        *reinterpret_cast<float4*>(&ks[row][c4]) = make_float4(e0*inv, e1*inv, e2*inv, e3*inv);
        *reinterpret_cast<float4*>(&vs[row][c4]) = make_float4(v01.x, v01.y, v23.x, v23.y);
        __syncthreads();

#pragma unroll
        for (int r8 = 0; r8 < 8; r8++) {
            int rr = g * 8 + r8;
            float4 kc = *reinterpret_cast<float4*>(&ks[rr][c0]);
            float4 vd = *reinterpret_cast<float4*>(&vs[rr][d0]);
            acc[0][0] += kc.x * vd.x; acc[0][1] += kc.x * vd.y;
            acc[0][2] += kc.x * vd.z; acc[0][3] += kc.x * vd.w;
            acc[1][0] += kc.y * vd.x; acc[1][1] += kc.y * vd.y;
            acc[1][2] += kc.y * vd.z; acc[1][3] += kc.y * vd.w;
            acc[2][0] += kc.z * vd.x; acc[2][1] += kc.z * vd.y;
            acc[2][2] += kc.z * vd.z; acc[2][3] += kc.z * vd.w;
            acc[3][0] += kc.w * vd.x; acc[3][1] += kc.w * vd.y;
            acc[3][2] += kc.w * vd.z; acc[3][3] += kc.w * vd.w;
        }
    }

    if (g > 0) {
#pragma unroll
        for (int i = 0; i < 4; i++)
            *reinterpret_cast<float4*>(&red[g-1][slot][i*4]) =
                make_float4(acc[i][0], acc[i][1], acc[i][2], acc[i][3]);
    }
    __syncthreads();
    if (g == 0) {
#pragma unroll
        for (int gg = 0; gg < 3; gg++)
#pragma unroll
            for (int i = 0; i < 4; i++) {
                float4 r4 = *reinterpret_cast<float4*>(&red[gg][slot][i*4]);
                acc[i][0] += r4.x; acc[i][1] += r4.y; acc[i][2] += r4.z; acc[i][3] += r4.w;
            }
        float* op = g_ctxp + ((size_t)branch * 1024 + x) * 1024;
#pragma unroll
        for (int i = 0; i < 4; i++)
            *reinterpret_cast<float4*>(op + (c0 + i) * 32 + d0) =
                make_float4(acc[i][0], acc[i][1], acc[i][2], acc[i][3]);
    }
}

// grid (BB*NH, 3), 1024 threads
__global__ void __launch_bounds__(1024)
ctx_reduce_kernel()
{
    int bh = blockIdx.x, branch = blockIdx.y, tid = threadIdx.x;
    int b = bh >> 3, h = bh & 7;
    size_t base_x = (size_t)b * 256 + h * 32;
    float s = 0.f;
    for (int ch = 0; ch < CCH; ch++)
        s += g_ctxp[((size_t)branch * 1024 + base_x + ch) * 1024 + tid];
    g_ctx[((size_t)b * 24 + branch * 8 + h) * 1024 + tid] = s;
}

// ===================== E[b][j][h*32+c] = (1/1024) * sum_d ctx[b,h,c,d]*wf[j][h*32+d]
// grid (24, 4), 256 threads (j)
__global__ void __launch_bounds__(256)
ctxE_kernel(const __half* __restrict__ wf)
{
    __shared__ float cs[32][32];
    int h = blockIdx.x, b = blockIdx.y, j = threadIdx.x;

    const float* cp = g_ctx + ((size_t)b * 24 + h) * 1024;
#pragma unroll
    for (int u = 0; u < 4; u++)
        cs[(j * 4 + u) >> 5][(j * 4 + u) & 31] = cp[j * 4 + u];
    __syncthreads();

    float wd[32];
#pragma unroll
    for (int d = 0; d < 32; d++)
        wd[d] = __half2float(wf[(size_t)j * 768 + h * 32 + d]);

    __half* ep = g_E + ((size_t)b * 256 + j) * 768 + h * 32;
#pragma unroll
    for (int c = 0; c < 32; c++) {
        float a = 0.f;
#pragma unroll
        for (int d = 0; d < 32; d++) a += cs[c][d] * wd[d];
        ep[c] = __float2half_rn(a * (1.f / 1024.f));
    }
}

// ===================== launcher =====================
extern "C" void kernel_launch(void* const* d_in, const int* in_sizes, int n_in,
                              void* d_out, int out_size)
{
    const float* f[4]   = {(const float*)d_in[0], (const float*)d_in[1],
                           (const float*)d_in[2], (const float*)d_in[3]};
    const float* fpe[4] = {(const float*)d_in[4], (const float*)d_in[5],
                           (const float*)d_in[6], (const float*)d_in[7]};
    const float* Wq  = (const float*)d_in[8];
    const float* bq  = (const float*)d_in[9];
    const float* Wk  = (const float*)d_in[10];
    const float* bk  = (const float*)d_in[11];
    const float* Wv  = (const float*)d_in[12];
    const float* bv  = (const float*)d_in[13];
    const float* Wrp = (const float*)d_in[14];
    const float* brp = (const float*)d_in[15];
    float* out = (float*)d_out;

    cudaFuncSetAttribute(gemm_f16out, cudaFuncAttributeMaxDynamicSharedMemorySize, GEMM_SMEM);
    cudaFuncSetAttribute(gemm_f32out, cudaFuncAttributeMaxDynamicSharedMemorySize, GEMM_SMEM);
    cudaFuncSetAttribute(gemm_kv,     cudaFuncAttributeMaxDynamicSharedMemorySize, GEMM_SMEM);

    __half *abuf, *wbuf, *q16, *sq, *E;
    cudaGetSymbolAddress((void**)&abuf, g_a);
    cudaGetSymbolAddress((void**)&wbuf, g_w);
    cudaGetSymbolAddress((void**)&q16,  g_q16);
    cudaGetSymbolAddress((void**)&sq,   g_sq);
    cudaGetSymbolAddress((void**)&E,    g_E);

    const size_t AS = (size_t)MTOT * 256;
    const int n4 = MTOT * DIM / 4;
    const int pb = n4 / 256;

    __half* wq = wbuf;                    // [768][256]
    __half* wk = wbuf + 196608;           // 3 x [256][256], then wv 3 x
    __half* wf = wbuf + 589824;           // [256][768]

    // launches 1-5
    prep_q<<<pb, 256>>>(f[0], fpe[0], abuf, n4);
    prep_w_all<<<3072, 256>>>(Wq, Wk, Wv, Wrp, wbuf);
    for (int i = 1; i <= 3; i++)
        prep_kv<<<pb, 256>>>(f[i], fpe[i], abuf + i * AS, abuf + (3 + i) * AS, n4);

    // launch 6 (ncu slot): qall = q_in @ [Wq0|Wq1|Wq2] -> fp16
    gemm_f16out<<<dim3(6, MTOT/128, 1), 256, GEMM_SMEM>>>(abuf, 256, wq, 256, bq, q16, 768, 8);

    // all 6 k/v GEMMs, fp16 out
    gemm_kv<<<dim3(2, MTOT/128, 6), 256, GEMM_SMEM>>>(abuf, wk, bk, bv);

    // ctx for all branches
    ctx_part_kernel  <<<dim3(BB * NH * CCH, 3), 256>>>();
    ctx_reduce_kernel<<<dim3(BB * NH, 3), 1024>>>();

    // q sumexp + softq
    qsum_part_kernel  <<<dim3(BB, QCH, 3), 256>>>();
    qsum_reduce_kernel<<<dim3(BB, 3), 256>>>();
    softq_kernel<<<MTOT * 768 / 8 / 256, 256>>>();

    // effective final weights, then out = softq @ E[b] + brp
    ctxE_kernel<<<dim3(24, BB), 256>>>(wf);
    gemm_f32out<<<dim3(2, MTOT/128, 1), 256, GEMM_SMEM>>>(sq, 768, E, 768, (size_t)256*768,
                                                          brp, out, 256, 24);
}

// round 9
// speedup vs baseline: 5.2683x; 1.0925x over previous
#include <cuda_runtime.h>
#include <cuda_fp16.h>
#include <cstdint>

#define BB   4
#define SEQ  8192
#define DIM  256
#define NH   8
#define HD   32
#define MTOT (BB*SEQ)        // 32768
#define CCH  32

// ===================== scratch (device globals) =====================
__device__ __half g_a[7ull * MTOT * 256];        // fp16 activations: q_in, k2..k4, v2..v4
__device__ __half g_q16[(size_t)MTOT * 768];     // fp16 expq = exp(q)/32
__device__ __half g_w[786432];                   // fp16 weights: wq|wk,wv|wf(256x768)
__device__ __half g_E[4ull * 256 * 768];         // per-batch effective final weights (inv folded)
__device__ __half g_k16[3ull * MTOT * DIM];
__device__ __half g_v16[3ull * MTOT * DIM];
__device__ float g_ctxp[3ull * BB * NH * CCH * HD * HD];
__device__ float g_qs  [BB * 768];               // 1 / sum(exp(q)/32)
__device__ float g_qsp [256 * 768];              // per-row-block column partials

// ===================== helpers =====================
__device__ __forceinline__ uint32_t smem_u32(const void* p){
    uint32_t a;
    asm("{ .reg .u64 t; cvta.to.shared.u64 t, %1; cvt.u32.u64 %0, t; }" : "=r"(a) : "l"(p));
    return a;
}
__device__ __forceinline__ void cp16(uint32_t dst, const void* src){
    asm volatile("cp.async.cg.shared.global [%0], [%1], 16;" :: "r"(dst), "l"(src) : "memory");
}
__device__ __forceinline__ void cp_commit(){ asm volatile("cp.async.commit_group;" ::: "memory"); }
__device__ __forceinline__ void cp_wait1(){ asm volatile("cp.async.wait_group 1;" ::: "memory"); }
__device__ __forceinline__ void cp_wait0(){ asm volatile("cp.async.wait_group 0;" ::: "memory"); }

__device__ __forceinline__ void ldsm4(uint32_t& r0, uint32_t& r1, uint32_t& r2, uint32_t& r3, uint32_t addr){
    asm volatile("ldmatrix.sync.aligned.m8n8.x4.shared.b16 {%0,%1,%2,%3}, [%4];"
        : "=r"(r0), "=r"(r1), "=r"(r2), "=r"(r3) : "r"(addr));
}
__device__ __forceinline__ void mma16816(float* d, const uint32_t* a, const uint32_t* b){
    asm volatile("mma.sync.aligned.m16n8k16.row.col.f32.f16.f16.f32 "
        "{%0,%1,%2,%3}, {%4,%5,%6,%7}, {%8,%9}, {%0,%1,%2,%3};"
        : "+f"(d[0]), "+f"(d[1]), "+f"(d[2]), "+f"(d[3])
        : "r"(a[0]), "r"(a[1]), "r"(a[2]), "r"(a[3]), "r"(b[0]), "r"(b[1]));
}

// ===================== GEMM core (macro-shared mainloop) =====================
#define STG_BYTES 20480
#define GEMM_SMEM (3 * STG_BYTES)

#define GEMM_BODY(A, lda, B, ldb, nkc)                                          \
    const int tid  = threadIdx.x;                                               \
    const int lane = tid & 31, wid = tid >> 5;                                  \
    const int wm = wid >> 2, wn = wid & 3;                                      \
    const int row0 = blockIdx.y * 128;                                          \
    const int col0 = blockIdx.x * 128;                                          \
    float acc[4][4][4];                                                         \
    _Pragma("unroll") for (int i = 0; i < 4; i++)                               \
    _Pragma("unroll") for (int j = 0; j < 4; j++)                               \
    _Pragma("unroll") for (int v = 0; v < 4; v++) acc[i][j][v] = 0.f;           \
    const uint32_t smem_base = smem_u32(smem);                                  \
    const int ch0 = tid * 2;                                                    \
    auto prefetch = [&](int kc) {                                               \
        int s = kc % 3;                                                         \
        uint32_t As = smem_base + s * STG_BYTES;                                \
        uint32_t Bs = As + 10240;                                               \
        _Pragma("unroll") for (int t = 0; t < 2; t++) {                         \
            int ch = ch0 + t;                                                   \
            int r = ch >> 2, c = ch & 3;                                        \
            cp16(As + r * 80 + c * 16, A + (size_t)(row0 + r) * lda + kc * 32 + c * 8); \
            cp16(Bs + r * 80 + c * 16, B + (size_t)(col0 + r) * ldb + kc * 32 + c * 8); \
        }                                                                       \
        cp_commit();                                                            \
    };                                                                          \
    prefetch(0);                                                                \
    if (nkc > 1) prefetch(1);                                                   \
    const int arow = lane & 15, acolh = (lane >> 4) * 8;                        \
    const int bn   = (lane & 7) + (lane >> 4) * 8;                              \
    const int bkh  = ((lane >> 3) & 1) * 8;                                     \
    for (int kc = 0; kc < nkc; kc++) {                                          \
        if (kc + 1 < nkc) cp_wait1(); else cp_wait0();                          \
        __syncthreads();                                                        \
        if (kc + 2 < nkc) prefetch(kc + 2);                                     \
        int s = kc % 3;                                                         \
        uint32_t As = smem_base + s * STG_BYTES;                                \
        uint32_t Bs = As + 10240;                                               \
        _Pragma("unroll") for (int kk = 0; kk < 32; kk += 16) {                 \
            uint32_t af[4][4];                                                  \
            _Pragma("unroll") for (int i = 0; i < 4; i++) {                     \
                uint32_t addr = As + (wm * 64 + i * 16 + arow) * 80 + (kk + acolh) * 2; \
                ldsm4(af[i][0], af[i][1], af[i][2], af[i][3], addr);            \
            }                                                                   \
            uint32_t bf[4][2];                                                  \
            _Pragma("unroll") for (int jp = 0; jp < 2; jp++) {                  \
                uint32_t addr = Bs + (wn * 32 + jp * 16 + bn) * 80 + (kk + bkh) * 2; \
                ldsm4(bf[2*jp][0], bf[2*jp][1], bf[2*jp+1][0], bf[2*jp+1][1], addr); \
            }                                                                   \
            _Pragma("unroll") for (int i = 0; i < 4; i++)                       \
            _Pragma("unroll") for (int j = 0; j < 4; j++)                       \
                mma16816(acc[i][j], af[i], bf[j]);                              \
        }                                                                       \
    }

// qall GEMM with fused exp + column partial sums. C = exp(A@B^T + bias)/32 (fp16);
// g_qsp[blockIdx.y*768 + col] = per-128-row-block column sums (fp32, pre-rounding).
__global__ void __launch_bounds__(256, 2)
gemm_expq(const __half* __restrict__ Ag, int lda,
          const __half* __restrict__ Bg, int ldb,
          const float* __restrict__ bias, __half* __restrict__ C, int N, int KH)
{
    extern __shared__ __align__(16) char smem[];
    GEMM_BODY(Ag, lda, Bg, ldb, KH)

    __syncthreads();                                  // smem now free for reuse
    float* red = reinterpret_cast<float*>(smem);      // [16][128]
    const int g = lane >> 2, tg = lane & 3;
    float bb0[4], bb1[4];
#pragma unroll
    for (int j = 0; j < 4; j++) {
        int c = col0 + wn * 32 + j * 8 + 2 * tg;
        bb0[j] = bias[c]; bb1[j] = bias[c + 1];
    }
    float cs0[4] = {0.f,0.f,0.f,0.f}, cs1[4] = {0.f,0.f,0.f,0.f};
#pragma unroll
    for (int i = 0; i < 4; i++) {
        int r = row0 + wm * 64 + i * 16 + g;
#pragma unroll
        for (int j = 0; j < 4; j++) {
            int c = col0 + wn * 32 + j * 8 + 2 * tg;
            float e0 = __expf(acc[i][j][0] + bb0[j]) * 0.03125f;
            float e1 = __expf(acc[i][j][1] + bb1[j]) * 0.03125f;
            float e2 = __expf(acc[i][j][2] + bb0[j]) * 0.03125f;
            float e3 = __expf(acc[i][j][3] + bb1[j]) * 0.03125f;
            *reinterpret_cast<__half2*>(C + (size_t)r * N + c)       = __floats2half2_rn(e0, e1);
            *reinterpret_cast<__half2*>(C + (size_t)(r + 8) * N + c) = __floats2half2_rn(e2, e3);
            cs0[j] += e0 + e2;
            cs1[j] += e1 + e3;
        }
    }
#pragma unroll
    for (int j = 0; j < 4; j++) {
        int lc = wn * 32 + j * 8 + 2 * tg;
        red[(wm * 8 + g) * 128 + lc]     = cs0[j];
        red[(wm * 8 + g) * 128 + lc + 1] = cs1[j];
    }
    __syncthreads();
    if (tid < 128) {
        float s = 0.f;
#pragma unroll
        for (int u = 0; u < 16; u++) s += red[u * 128 + tid];
        g_qsp[(size_t)blockIdx.y * 768 + col0 + tid] = s;
    }
}

// fp32-output GEMM with per-batch B (final): B += (blockIdx.y>>6)*bstride
__global__ void __launch_bounds__(256, 2)
gemm_f32out(const __half* __restrict__ Ag, int lda,
            const __half* __restrict__ Bg0, int ldb, size_t bstride,
            const float* __restrict__ bias, float* __restrict__ C, int N, int KH)
{
    extern __shared__ __align__(16) char smem[];
    const __half* Bg = Bg0 + (size_t)(blockIdx.y >> 6) * bstride;
    GEMM_BODY(Ag, lda, Bg, ldb, KH)

    const int g = lane >> 2, tg = lane & 3;
    float2 bb[4];
#pragma unroll
    for (int j = 0; j < 4; j++) {
        int c = col0 + wn * 32 + j * 8 + 2 * tg;
        bb[j] = make_float2(bias[c], bias[c + 1]);
    }
#pragma unroll
    for (int i = 0; i < 4; i++) {
        int r = row0 + wm * 64 + i * 16 + g;
#pragma unroll
        for (int j = 0; j < 4; j++) {
            int c = col0 + wn * 32 + j * 8 + 2 * tg;
            *reinterpret_cast<float2*>(C + (size_t)r * N + c) =
                make_float2(acc[i][j][0] + bb[j].x, acc[i][j][1] + bb[j].y);
            *reinterpret_cast<float2*>(C + (size_t)(r + 8) * N + c) =
                make_float2(acc[i][j][2] + bb[j].x, acc[i][j][3] + bb[j].y);
        }
    }
}

// batched k/v GEMM: z = 0..5 -> branch = z%3, kv = z/3; fp16 output
__global__ void __launch_bounds__(256, 2)
gemm_kv(const __half* __restrict__ abuf, const __half* __restrict__ wkv,
        const float* __restrict__ bk, const float* __restrict__ bv)
{
    extern __shared__ __align__(16) char smem[];
    const int z = blockIdx.z;
    const int branch = z % 3, kv = z / 3;
    const __half* Ag = abuf + (size_t)(1 + branch + 3 * kv) * MTOT * 256;
    const __half* Bg = wkv + (size_t)(3 * kv + branch) * 65536;
    const float* bias = (kv ? bv : bk) + branch * 256;
    __half* C = (kv ? g_v16 : g_k16) + (size_t)branch * MTOT * 256;

    GEMM_BODY(Ag, 256, Bg, 256, 8)

    const int g = lane >> 2, tg = lane & 3;
    float2 bb[4];
#pragma unroll
    for (int j = 0; j < 4; j++) {
        int c = col0 + wn * 32 + j * 8 + 2 * tg;
        bb[j] = make_float2(bias[c], bias[c + 1]);
    }
#pragma unroll
    for (int i = 0; i < 4; i++) {
        int r = row0 + wm * 64 + i * 16 + g;
#pragma unroll
        for (int j = 0; j < 4; j++) {
            int c = col0 + wn * 32 + j * 8 + 2 * tg;
            *reinterpret_cast<__half2*>(C + (size_t)r * 256 + c) =
                __floats2half2_rn(acc[i][j][0] + bb[j].x, acc[i][j][1] + bb[j].y);
            *reinterpret_cast<__half2*>(C + (size_t)(r + 8) * 256 + c) =
                __floats2half2_rn(acc[i][j][2] + bb[j].x, acc[i][j][3] + bb[j].y);
        }
    }
}

// ===================== prep kernels =====================
__device__ __forceinline__ uint2 cvt4(float4 x)
{
    union { __half2 h2[2]; uint2 u; } U;
    U.h2[0] = __floats2half2_rn(x.x, x.y);
    U.h2[1] = __floats2half2_rn(x.z, x.w);
    return U.u;
}

__global__ void __launch_bounds__(256)
prep_q(const float* __restrict__ a, const float* __restrict__ b,
       __half* __restrict__ o, int n4)
{
    int i = blockIdx.x * 256 + threadIdx.x;
    if (i >= n4) return;
    float4 x = reinterpret_cast<const float4*>(a)[i];
    float4 y = reinterpret_cast<const float4*>(b)[i];
    x.x += y.x; x.y += y.y; x.z += y.z; x.w += y.w;
    reinterpret_cast<uint2*>(o)[i] = cvt4(x);
}

// batched over branches: blockIdx.y = 0..2
__global__ void __launch_bounds__(256)
prep_kv_b(const float* __restrict__ f2, const float* __restrict__ f3, const float* __restrict__ f4,
          const float* __restrict__ p2, const float* __restrict__ p3, const float* __restrict__ p4,
          __half* __restrict__ abuf, int n4)
{
    int br = blockIdx.y;
    const float* f  = (br == 0) ? f2 : (br == 1) ? f3 : f4;
    const float* pe = (br == 0) ? p2 : (br == 1) ? p3 : p4;
    __half* ok = abuf + (size_t)(1 + br) * MTOT * 256;
    __half* ov = abuf + (size_t)(4 + br) * MTOT * 256;

    int i = blockIdx.x * 256 + threadIdx.x;
    if (i >= n4) return;
    float4 x = reinterpret_cast<const float4*>(f)[i];
    float4 y = reinterpret_cast<const float4*>(pe)[i];
    float4 k = make_float4(x.x + y.x, x.y + y.y, x.z + y.z, x.w + y.w);
    reinterpret_cast<uint2*>(ok)[i] = cvt4(k);
    reinterpret_cast<uint2*>(ov)[i] = cvt4(x);
}

__global__ void __launch_bounds__(256)
prep_w_all(const float* __restrict__ Wq, const float* __restrict__ Wk,
           const float* __restrict__ Wv, const float* __restrict__ Wrp,
           __half* __restrict__ o)
{
    int t = blockIdx.x * 256 + threadIdx.x;
    if (t < 589824) {
        int mat = t >> 16, idx = t & 65535;
        int n = idx >> 8, k = idx & 255;
        const float* W = (mat < 3) ? Wq + (size_t)mat * 65536
                       : (mat < 6) ? Wk + (size_t)(mat - 3) * 65536
                                   : Wv + (size_t)(mat - 6) * 65536;
        o[(size_t)mat * 65536 + (size_t)n * 256 + k] = __float2half_rn(W[k * 256 + n]);
    } else {
        int idx = t - 589824;
        int n = idx / 768, k = idx - n * 768;
        o[589824 + (size_t)n * 768 + k] = __float2half_rn(Wrp[(size_t)k * 256 + n]);
    }
}

// ===================== qsum reduce: inv[b,c] = 1 / sum over 64 row-blocks ====
__global__ void qsum_reduce_kernel()
{
    int b = blockIdx.x, c = blockIdx.y * 256 + threadIdx.x;
    float s = 0.f;
#pragma unroll 4
    for (int rb = 0; rb < 64; rb++)
        s += g_qsp[(size_t)(b * 64 + rb) * 768 + c];
    g_qs[b * 768 + c] = 1.f / s;
}

// ===================== ctx = softmax_c(k)^T v — register-blocked =============
// grid (1024, 3): x -> (b, h, chunk), y = branch. 256 threads.
__global__ void __launch_bounds__(256)
ctx_part_kernel()
{
    __shared__ float ks[32][40];
    __shared__ float vs[32][40];
    __shared__ float red[3][64][16];

    int x = blockIdx.x, branch = blockIdx.y;
    int chunk = x & 31, h = (x >> 5) & 7, b = x >> 8;
    int tid = threadIdx.x;
    int row = tid >> 3, c4 = (tid & 7) * 4;
    int g = tid >> 6, slot = tid & 63;
    int c0 = (slot >> 3) * 4, d0 = (slot & 7) * 4;

    float acc[4][4];
#pragma unroll
    for (int i = 0; i < 4; i++)
#pragma unroll
        for (int j = 0; j < 4; j++) acc[i][j] = 0.f;

    const size_t base = ((size_t)branch * MTOT + (size_t)b * SEQ + (size_t)chunk * 256) * DIM + h * HD;

    for (int t = 0; t < 8; t++) {
        const __half* kp = g_k16 + base + (size_t)(t * 32 + row) * DIM + c4;
        const __half* vp = g_v16 + base + (size_t)(t * 32 + row) * DIM + c4;
        uint2 ku = *reinterpret_cast<const uint2*>(kp);
        uint2 vu = *reinterpret_cast<const uint2*>(vp);
        float2 k01 = __half22float2(*reinterpret_cast<__half2*>(&ku.x));
        float2 k23 = __half22float2(*reinterpret_cast<__half2*>(&ku.y));
        float2 v01 = __half22float2(*reinterpret_cast<__half2*>(&vu.x));
        float2 v23 = __half22float2(*reinterpret_cast<__half2*>(&vu.y));

        float e0 = __expf(k01.x), e1 = __expf(k01.y);
        float e2 = __expf(k23.x), e3 = __expf(k23.y);
        float s = (e0 + e1) + (e2 + e3);
#pragma unroll
        for (int o = 1; o < 8; o <<= 1) s += __shfl_xor_sync(0xffffffffu, s, o);
        float inv = 1.f / s;

        __syncthreads();
        *reinterpret_cast<float4*>(&ks[row][c4]) = make_float4(e0*inv, e1*inv, e2*inv, e3*inv);
        *reinterpret_cast<float4*>(&vs[row][c4]) = make_float4(v01.x, v01.y, v23.x, v23.y);
        __syncthreads();

#pragma unroll
        for (int r8 = 0; r8 < 8; r8++) {
            int rr = g * 8 + r8;
            float4 kc = *reinterpret_cast<float4*>(&ks[rr][c0]);
            float4 vd = *reinterpret_cast<float4*>(&vs[rr][d0]);
            acc[0][0] += kc.x * vd.x; acc[0][1] += kc.x * vd.y;
            acc[0][2] += kc.x * vd.z; acc[0][3] += kc.x * vd.w;
            acc[1][0] += kc.y * vd.x; acc[1][1] += kc.y * vd.y;
            acc[1][2] += kc.y * vd.z; acc[1][3] += kc.y * vd.w;
            acc[2][0] += kc.z * vd.x; acc[2][1] += kc.z * vd.y;
            acc[2][2] += kc.z * vd.z; acc[2][3] += kc.z * vd.w;
            acc[3][0] += kc.w * vd.x; acc[3][1] += kc.w * vd.y;
            acc[3][2] += kc.w * vd.z; acc[3][3] += kc.w * vd.w;
        }
    }

    if (g > 0) {
#pragma unroll
        for (int i = 0; i < 4; i++)
            *reinterpret_cast<float4*>(&red[g-1][slot][i*4]) =
                make_float4(acc[i][0], acc[i][1], acc[i][2], acc[i][3]);
    }
    __syncthreads();
    if (g == 0) {
#pragma unroll
        for (int gg = 0; gg < 3; gg++)
#pragma unroll
            for (int i = 0; i < 4; i++) {
                float4 r4 = *reinterpret_cast<float4*>(&red[gg][slot][i*4]);
                acc[i][0] += r4.x; acc[i][1] += r4.y; acc[i][2] += r4.z; acc[i][3] += r4.w;
            }
        float* op = g_ctxp + ((size_t)branch * 1024 + x) * 1024;
#pragma unroll
        for (int i = 0; i < 4; i++)
            *reinterpret_cast<float4*>(op + (c0 + i) * 32 + d0) =
                make_float4(acc[i][0], acc[i][1], acc[i][2], acc[i][3]);
    }
}

// ===================== E[b][j][h24*32+c] = inv[b,h24*32+c] * sum_d ctx*wf ====
// Also folds the CCH-chunk reduction of g_ctxp. grid (24, 4), 256 threads.
__global__ void __launch_bounds__(256)
ctxE_kernel(const __half* __restrict__ wf)
{
    __shared__ float cs[32][32];
    int h24 = blockIdx.x, b = blockIdx.y, j = threadIdx.x;
    int branch = h24 >> 3, hbr = h24 & 7;
    size_t pbase = (size_t)branch * 1024 + (size_t)b * 256 + hbr * 32;

    float local[4] = {0.f, 0.f, 0.f, 0.f};
    for (int ch = 0; ch < 32; ch++) {
        const float* cp = g_ctxp + (pbase + ch) * 1024 + j * 4;
#pragma unroll
        for (int u = 0; u < 4; u++) local[u] += cp[u];
    }
#pragma unroll
    for (int u = 0; u < 4; u++) {
        int idx = j * 4 + u;
        cs[idx >> 5][idx & 31] = local[u];
    }
    __syncthreads();

    float wd[32];
#pragma unroll
    for (int d = 0; d < 32; d++)
        wd[d] = __half2float(wf[(size_t)j * 768 + h24 * 32 + d]);

    const float* invp = g_qs + b * 768 + h24 * 32;
    __half* ep = g_E + ((size_t)b * 256 + j) * 768 + h24 * 32;
#pragma unroll
    for (int c = 0; c < 32; c++) {
        float a = 0.f;
#pragma unroll
        for (int d = 0; d < 32; d++) a += cs[c][d] * wd[d];
        ep[c] = __float2half_rn(a * invp[c]);
    }
}

// ===================== launcher =====================
extern "C" void kernel_launch(void* const* d_in, const int* in_sizes, int n_in,
                              void* d_out, int out_size)
{
    const float* f[4]   = {(const float*)d_in[0], (const float*)d_in[1],
                           (const float*)d_in[2], (const float*)d_in[3]};
    const float* fpe[4] = {(const float*)d_in[4], (const float*)d_in[5],
                           (const float*)d_in[6], (const float*)d_in[7]};
    const float* Wq  = (const float*)d_in[8];
    const float* bq  = (const float*)d_in[9];
    const float* Wk  = (const float*)d_in[10];
    const float* bk  = (const float*)d_in[11];
    const float* Wv  = (const float*)d_in[12];
    const float* bv  = (const float*)d_in[13];
    const float* Wrp = (const float*)d_in[14];
    const float* brp = (const float*)d_in[15];
    float* out = (float*)d_out;

    cudaFuncSetAttribute(gemm_expq,   cudaFuncAttributeMaxDynamicSharedMemorySize, GEMM_SMEM);
    cudaFuncSetAttribute(gemm_f32out, cudaFuncAttributeMaxDynamicSharedMemorySize, GEMM_SMEM);
    cudaFuncSetAttribute(gemm_kv,     cudaFuncAttributeMaxDynamicSharedMemorySize, GEMM_SMEM);

    __half *abuf, *wbuf, *q16, *E;
    cudaGetSymbolAddress((void**)&abuf, g_a);
    cudaGetSymbolAddress((void**)&wbuf, g_w);
    cudaGetSymbolAddress((void**)&q16,  g_q16);
    cudaGetSymbolAddress((void**)&E,    g_E);

    const int n4 = MTOT * DIM / 4;
    const int pb = n4 / 256;

    __half* wq = wbuf;                    // [768][256]
    __half* wk = wbuf + 196608;           // 3 x [256][256], then wv 3 x
    __half* wf = wbuf + 589824;           // [256][768]

    // launches 1-3
    prep_q<<<pb, 256>>>(f[0], fpe[0], abuf, n4);
    prep_w_all<<<3072, 256>>>(Wq, Wk, Wv, Wrp, wbuf);
    prep_kv_b<<<dim3(pb, 3), 256>>>(f[1], f[2], f[3], fpe[1], fpe[2], fpe[3], abuf, n4);

    // launch 4 (ncu slot): qall GEMM with fused exp + column sums
    gemm_expq<<<dim3(6, MTOT/128, 1), 256, GEMM_SMEM>>>(abuf, 256, wq, 256, bq, q16, 768, 8);

    // all 6 k/v GEMMs, fp16 out
    gemm_kv<<<dim3(2, MTOT/128, 6), 256, GEMM_SMEM>>>(abuf, wk, bk, bv);

    // ctx partials for all branches
    ctx_part_kernel<<<dim3(BB * NH * CCH, 3), 256>>>();

    // q-softmax normalization constants
    qsum_reduce_kernel<<<dim3(BB, 3), 256>>>();

    // effective final weights (ctx reduce + Wrp fold + inv fold)
    ctxE_kernel<<<dim3(24, BB), 256>>>(wf);

    // out = expq @ E[b] + brp
    gemm_f32out<<<dim3(2, MTOT/128, 1), 256, GEMM_SMEM>>>(q16, 768, E, 768, (size_t)256*768,
                                                          brp, out, 256, 24);
}